// round 3
// baseline (speedup 1.0000x reference)
#include <cuda_runtime.h>
#include <cuda_bf16.h>
#include <math.h>

// ---------------- problem constants ----------------
constexpr int B_ = 2;
constexpr int S_ = 2048;
constexpr int D_ = 2048;
constexpr int H_ = 16;
constexpr int Q_LORA = 1536;
constexpr int KV_LORA = 512;
constexpr int D_NOPE = 128;
constexpr int D_ROPE = 64;
constexpr int D_QK = D_NOPE + D_ROPE;   // 192
constexpr int D_V = 128;
constexpr int BS = B_ * S_;             // 4096
constexpr int BH = B_ * H_;             // 32

// ---------------- scratch (device globals; no dynamic alloc allowed) ----------------
__device__ float g_qa   [(size_t)BS * Q_LORA];
__device__ float g_qan  [(size_t)BS * Q_LORA];
__device__ float g_qfull[(size_t)BS * (H_ * D_QK)];
__device__ float g_kva  [(size_t)BS * (KV_LORA + D_ROPE)];
__device__ float g_kvc  [(size_t)BS * KV_LORA];
__device__ float g_kvb  [(size_t)BS * (H_ * (D_NOPE + D_V))];
__device__ float g_qh   [(size_t)BH * S_ * D_QK];
__device__ float g_kh   [(size_t)BH * S_ * D_QK];
__device__ float g_vh   [(size_t)BH * S_ * D_V];
__device__ float g_scores[(size_t)BH * S_ * S_];
__device__ float g_attn [(size_t)BS * (H_ * D_V)];

// ---------------- generic batched strided SGEMM ----------------
// C[M,N] = alpha * A[M,K] x op(B)
//   flags bit2 set  -> B is [N,K] row-major (C = A*B^T)    (NT)
//   flags bit2 clr  -> B is [K,N] row-major (C = A*B)      (NN)
//   flags bit0      -> causal tile skip (skip tile if n0 > m0)
//   flags bit1      -> limit K to m0+BM (P*V causal bound)
// batch offset for X: (z % innerN)*isX + (z / innerN)*osX
#define GBM 128
#define GBN 128
#define GBK 16

__global__ void __launch_bounds__(256) gemm_kernel(
    const float* __restrict__ A, const float* __restrict__ Bm, float* __restrict__ C,
    int M, int N, int K, int lda, int ldb, int ldc,
    long long isA, long long osA, long long isB, long long osB,
    long long isC, long long osC, int innerN,
    float alpha, int flags)
{
    int z = blockIdx.z;
    A  += (long long)(z % innerN) * isA + (long long)(z / innerN) * osA;
    Bm += (long long)(z % innerN) * isB + (long long)(z / innerN) * osB;
    C  += (long long)(z % innerN) * isC + (long long)(z / innerN) * osC;

    int m0 = blockIdx.y * GBM;
    int n0 = blockIdx.x * GBN;
    if ((flags & 1) && n0 > m0) return;   // fully above causal diagonal
    int Keff = K;
    if (flags & 2) { int lim = m0 + GBM; if (lim < Keff) Keff = lim; }
    const bool nt = (flags & 4) != 0;

    __shared__ float As[GBK][GBM + 4];
    __shared__ float Bs[GBK][GBN + 4];

    int t  = threadIdx.x;
    int tx = t & 15;      // N direction
    int ty = t >> 4;      // M direction

    float acc[8][8];
#pragma unroll
    for (int i = 0; i < 8; i++)
#pragma unroll
        for (int j = 0; j < 8; j++) acc[i][j] = 0.0f;

    for (int k0 = 0; k0 < Keff; k0 += GBK) {
        // ---- load A tile (K-contiguous, float4 along K) ----
#pragma unroll
        for (int ld = 0; ld < 2; ld++) {
            int v  = t + ld * 256;
            int m  = v >> 2;
            int kq = (v & 3) << 2;
            float4 val = make_float4(0.f, 0.f, 0.f, 0.f);
            int gm = m0 + m;
            if (gm < M)
                val = *(const float4*)(A + (long long)gm * lda + (k0 + kq));
            As[kq    ][m] = val.x;
            As[kq + 1][m] = val.y;
            As[kq + 2][m] = val.z;
            As[kq + 3][m] = val.w;
        }
        // ---- load B tile ----
        if (nt) {
#pragma unroll
            for (int ld = 0; ld < 2; ld++) {
                int v  = t + ld * 256;
                int n  = v >> 2;
                int kq = (v & 3) << 2;
                float4 val = make_float4(0.f, 0.f, 0.f, 0.f);
                int gn = n0 + n;
                if (gn < N)
                    val = *(const float4*)(Bm + (long long)gn * ldb + (k0 + kq));
                Bs[kq    ][n] = val.x;
                Bs[kq + 1][n] = val.y;
                Bs[kq + 2][n] = val.z;
                Bs[kq + 3][n] = val.w;
            }
        } else {
#pragma unroll
            for (int ld = 0; ld < 2; ld++) {
                int v = t + ld * 256;
                int k = v >> 5;
                int n = (v & 31) << 2;
                float4 val = make_float4(0.f, 0.f, 0.f, 0.f);
                int gn = n0 + n;
                if (gn < N)
                    val = *(const float4*)(Bm + (long long)(k0 + k) * ldb + gn);
                *(float4*)&Bs[k][n] = val;
            }
        }
        __syncthreads();
        // ---- 8x8 microkernel ----
#pragma unroll
        for (int kk = 0; kk < GBK; kk++) {
            float4 a0 = *(const float4*)&As[kk][ty * 8];
            float4 a1 = *(const float4*)&As[kk][ty * 8 + 4];
            float4 b0 = *(const float4*)&Bs[kk][tx * 8];
            float4 b1 = *(const float4*)&Bs[kk][tx * 8 + 4];
            float a[8] = {a0.x, a0.y, a0.z, a0.w, a1.x, a1.y, a1.z, a1.w};
            float b[8] = {b0.x, b0.y, b0.z, b0.w, b1.x, b1.y, b1.z, b1.w};
#pragma unroll
            for (int i = 0; i < 8; i++)
#pragma unroll
                for (int j = 0; j < 8; j++)
                    acc[i][j] += a[i] * b[j];
        }
        __syncthreads();
    }
    // ---- store ----
#pragma unroll
    for (int i = 0; i < 8; i++) {
        int gm = m0 + ty * 8 + i;
        if (gm >= M) continue;
#pragma unroll
        for (int j = 0; j < 8; j++) {
            int gn = n0 + tx * 8 + j;
            if (gn < N)
                C[(long long)gm * ldc + gn] = alpha * acc[i][j];
        }
    }
}

// ---------------- RMSNorm (block per row) ----------------
__global__ void rmsnorm_kernel(const float* __restrict__ in, const float* __restrict__ w,
                               float* __restrict__ out, int width, int in_stride, int out_stride)
{
    long long row = blockIdx.x;
    const float* x = in + row * in_stride;
    float* o = out + row * out_stride;
    __shared__ float red[256];
    int t = threadIdx.x;
    float ss = 0.f;
    for (int i = t; i < width; i += 256) { float v = x[i]; ss += v * v; }
    red[t] = ss;
    __syncthreads();
    for (int s = 128; s > 0; s >>= 1) {
        if (t < s) red[t] += red[t + s];
        __syncthreads();
    }
    float scale = rsqrtf(red[0] / (float)width + 1e-6f);
    for (int i = t; i < width; i += 256) o[i] = x[i] * scale * w[i];
}

// ---------------- RoPE + head assembly ----------------
// qh/kh: [B,H,S,192], vh: [B,H,S,128]
__global__ void assemble_kernel(const float* __restrict__ q_full, const float* __restrict__ kv_a,
                                const float* __restrict__ kv_b, const float* __restrict__ freqs,
                                float* __restrict__ qh, float* __restrict__ kh, float* __restrict__ vh)
{
    int bs = blockIdx.x;           // 0..BS-1
    int h  = blockIdx.y;           // 0..H-1
    int s  = bs & (S_ - 1);
    int b  = bs >> 11;             // bs / S_
    const float* fr  = freqs + (long long)s * D_ROPE;            // [32][2] (cos,sin)
    long long hd = ((long long)(b * H_ + h) * S_ + s);
    float* qo = qh + hd * D_QK;
    float* ko = kh + hd * D_QK;
    float* vo = vh + hd * D_V;
    const float* qi  = q_full + (long long)bs * (H_ * D_QK) + h * D_QK;
    const float* kvb = kv_b  + (long long)bs * (H_ * (D_NOPE + D_V)) + h * (D_NOPE + D_V);
    const float* kpe = kv_a  + (long long)bs * (KV_LORA + D_ROPE) + KV_LORA;

    int t = threadIdx.x;           // 128 threads
    if (t < 128) {
        qo[t] = qi[t];
        ko[t] = kvb[t];
        vo[t] = kvb[D_NOPE + t];
    }
    if (t < 32) {
        float c  = fr[2 * t];
        float sn = fr[2 * t + 1];
        float x0 = qi[D_NOPE + 2 * t];
        float x1 = qi[D_NOPE + 2 * t + 1];
        qo[D_NOPE + 2 * t]     = x0 * c - x1 * sn;
        qo[D_NOPE + 2 * t + 1] = x0 * sn + x1 * c;
        float y0 = kpe[2 * t];
        float y1 = kpe[2 * t + 1];
        ko[D_NOPE + 2 * t]     = y0 * c - y1 * sn;
        ko[D_NOPE + 2 * t + 1] = y0 * sn + y1 * c;
    }
}

// ---------------- causal softmax (block per row); zeroes masked tail ----------------
__global__ void softmax_kernel(float* __restrict__ scores)
{
    int q = blockIdx.x;
    long long bh = blockIdx.y;
    float* row = scores + (bh * S_ + q) * (long long)S_;
    int len = q + 1;
    __shared__ float red[256];
    int t = threadIdx.x;
    float v[8];
    float mx = -1e30f;
#pragma unroll
    for (int j = 0; j < 8; j++) {
        int i = t + j * 256;
        v[j] = (i < len) ? row[i] : -1e30f;
        mx = fmaxf(mx, v[j]);
    }
    red[t] = mx;
    __syncthreads();
    for (int s = 128; s > 0; s >>= 1) {
        if (t < s) red[t] = fmaxf(red[t], red[t + s]);
        __syncthreads();
    }
    mx = red[0];
    __syncthreads();
    float sum = 0.f;
#pragma unroll
    for (int j = 0; j < 8; j++) {
        v[j] = __expf(v[j] - mx);   // masked lanes underflow to 0
        sum += v[j];
    }
    red[t] = sum;
    __syncthreads();
    for (int s = 128; s > 0; s >>= 1) {
        if (t < s) red[t] += red[t + s];
        __syncthreads();
    }
    float inv = 1.0f / red[0];
#pragma unroll
    for (int j = 0; j < 8; j++) {
        int i = t + j * 256;
        row[i] = (i < len) ? v[j] * inv : 0.0f;   // zero tail so P*V can run dense
    }
}

// ---------------- launch helper ----------------
static void launch_gemm(const float* A, const float* Bm, float* C,
                        int M, int N, int K, int lda, int ldb, int ldc,
                        long long isA, long long osA, long long isB, long long osB,
                        long long isC, long long osC, int innerN, int batches,
                        float alpha, int flags)
{
    dim3 grid((N + GBN - 1) / GBN, (M + GBM - 1) / GBM, batches);
    gemm_kernel<<<grid, 256>>>(A, Bm, C, M, N, K, lda, ldb, ldc,
                               isA, osA, isB, osB, isC, osC, innerN, alpha, flags);
}

extern "C" void kernel_launch(void* const* d_in, const int* in_sizes, int n_in,
                              void* d_out, int out_size)
{
    const float* x     = (const float*)d_in[0];
    const float* freqs = (const float*)d_in[1];
    const float* Wqa   = (const float*)d_in[2];
    const float* qlnw  = (const float*)d_in[3];
    const float* Wqb   = (const float*)d_in[4];
    const float* Wkva  = (const float*)d_in[5];
    const float* kvlnw = (const float*)d_in[6];
    const float* Wkvb  = (const float*)d_in[7];
    const float* Wo    = (const float*)d_in[8];
    float* out = (float*)d_out;

    float *qa, *qan, *qfull, *kva, *kvc, *kvb, *qh, *kh, *vh, *scores, *attn;
    cudaGetSymbolAddress((void**)&qa,     g_qa);
    cudaGetSymbolAddress((void**)&qan,    g_qan);
    cudaGetSymbolAddress((void**)&qfull,  g_qfull);
    cudaGetSymbolAddress((void**)&kva,    g_kva);
    cudaGetSymbolAddress((void**)&kvc,    g_kvc);
    cudaGetSymbolAddress((void**)&kvb,    g_kvb);
    cudaGetSymbolAddress((void**)&qh,     g_qh);
    cudaGetSymbolAddress((void**)&kh,     g_kh);
    cudaGetSymbolAddress((void**)&vh,     g_vh);
    cudaGetSymbolAddress((void**)&scores, g_scores);
    cudaGetSymbolAddress((void**)&attn,   g_attn);

    const float SCALE = 1.0f / sqrtf((float)D_QK);
    const int NT = 4, CAUSAL = 1, KLIMIT = 2;

    // 1. q_a = x @ Wqa^T                      [4096,1536] K=2048
    launch_gemm(x, Wqa, qa, BS, Q_LORA, D_, D_, D_, Q_LORA,
                0, 0, 0, 0, 0, 0, 1, 1, 1.0f, NT);
    // 2. RMSNorm q_a
    rmsnorm_kernel<<<BS, 256>>>(qa, qlnw, qan, Q_LORA, Q_LORA, Q_LORA);
    // 3. q_full = q_a_n @ Wqb^T               [4096,3072] K=1536
    launch_gemm(qan, Wqb, qfull, BS, H_ * D_QK, Q_LORA, Q_LORA, Q_LORA, H_ * D_QK,
                0, 0, 0, 0, 0, 0, 1, 1, 1.0f, NT);
    // 4. kv_a = x @ Wkva^T                    [4096,576] K=2048
    launch_gemm(x, Wkva, kva, BS, KV_LORA + D_ROPE, D_, D_, D_, KV_LORA + D_ROPE,
                0, 0, 0, 0, 0, 0, 1, 1, 1.0f, NT);
    // 5. RMSNorm kv_c (first 512 of each 576-wide row)
    rmsnorm_kernel<<<BS, 256>>>(kva, kvlnw, kvc, KV_LORA, KV_LORA + D_ROPE, KV_LORA);
    // 6. kv_b = kv_c @ Wkvb^T                 [4096,4096] K=512
    launch_gemm(kvc, Wkvb, kvb, BS, H_ * (D_NOPE + D_V), KV_LORA, KV_LORA, KV_LORA, H_ * (D_NOPE + D_V),
                0, 0, 0, 0, 0, 0, 1, 1, 1.0f, NT);
    // 7. RoPE + assemble per-head Q/K/V ([B,H,S,*])
    assemble_kernel<<<dim3(BS, H_), 128>>>(qfull, kva, kvb, freqs, qh, kh, vh);
    // 8. scores = SCALE * Q @ K^T, causal-skipped, batched over 32 (b,h)
    {
        long long isQ = (long long)S_ * D_QK;
        long long isS = (long long)S_ * S_;
        launch_gemm(qh, kh, scores, S_, S_, D_QK, D_QK, D_QK, S_,
                    isQ, isQ * H_, isQ, isQ * H_, isS, isS * H_, H_, BH,
                    SCALE, NT | CAUSAL);
    }
    // 9. causal softmax (+ zero masked tail)
    softmax_kernel<<<dim3(S_, BH), 256>>>(scores);
    // 10. attn[b,s,h*128] = P @ V  (K bounded per row-tile); C strided into [B,S,H*Dv]
    {
        long long isS = (long long)S_ * S_;
        long long isV = (long long)S_ * D_V;
        launch_gemm(scores, vh, attn, S_, D_V, S_, S_, D_V, H_ * D_V,
                    isS, isS * H_, isV, isV * H_,
                    (long long)D_V, (long long)S_ * (H_ * D_V), H_, BH,
                    1.0f, KLIMIT);  // NN mode
    }
    // 11. out = attn @ Wo^T                   [4096,2048] K=2048
    launch_gemm(attn, Wo, out, BS, D_, H_ * D_V, H_ * D_V, H_ * D_V, D_,
                0, 0, 0, 0, 0, 0, 1, 1, 1.0f, NT);
}

// round 6
// speedup vs baseline: 2.4291x; 2.4291x over previous
#include <cuda_runtime.h>
#include <cuda.h>
#include <cuda_bf16.h>
#include <math.h>
#include <cstdint>

// ---------------- problem constants ----------------
constexpr int B_ = 2;
constexpr int S_ = 2048;
constexpr int D_ = 2048;
constexpr int H_ = 16;
constexpr int Q_LORA = 1536;
constexpr int KV_LORA = 512;
constexpr int D_NOPE = 128;
constexpr int D_ROPE = 64;
constexpr int D_QK = D_NOPE + D_ROPE;   // 192
constexpr int D_V = 128;
constexpr int BS = B_ * S_;             // 4096
constexpr int BH = B_ * H_;             // 32

// ---------------- scratch (device globals) ----------------
__device__ float g_qa   [(size_t)BS * Q_LORA];
__device__ float g_qan  [(size_t)BS * Q_LORA];
__device__ float g_qfull[(size_t)BS * (H_ * D_QK)];
__device__ float g_kva  [(size_t)BS * (KV_LORA + D_ROPE)];
__device__ float g_kvc  [(size_t)BS * KV_LORA];
__device__ float g_kvb  [(size_t)BS * (H_ * (D_NOPE + D_V))];
__device__ float g_qh   [(size_t)BH * S_ * D_QK];
__device__ float g_kh   [(size_t)BH * S_ * D_QK];
__device__ float g_vhT  [(size_t)BH * D_V * S_];      // transposed: [b,h,d,s]
__device__ float g_scores[(size_t)BH * S_ * S_];
__device__ float g_attn [(size_t)BS * (H_ * D_V)];

// ---------------- helpers ----------------
__device__ __forceinline__ float f2tf32f(float f) {
    uint32_t r;
    asm("cvt.rna.tf32.f32 %0, %1;" : "=r"(r) : "f"(f));
    return __uint_as_float(r);
}

__device__ __forceinline__ void mma_tf32(float* c, const float* a, float b0, float b1) {
    asm volatile(
        "mma.sync.aligned.m16n8k8.row.col.f32.tf32.tf32.f32 "
        "{%0,%1,%2,%3}, {%4,%5,%6,%7}, {%8,%9}, {%0,%1,%2,%3};"
        : "+f"(c[0]), "+f"(c[1]), "+f"(c[2]), "+f"(c[3])
        : "r"(__float_as_uint(a[0])), "r"(__float_as_uint(a[1])),
          "r"(__float_as_uint(a[2])), "r"(__float_as_uint(a[3])),
          "r"(__float_as_uint(b0)), "r"(__float_as_uint(b1)));
}

// ---------------- tf32 mma.sync GEMM ----------------
// C[M,N] = alpha * A[M,K] * B[N,K]^T   (both K-major, NT)
// flags bit0: causal tile skip (n0 > m0). flags bit1: Keff = min(K, m0+128).
// batch z offsets: (z % innerN)*is + (z / innerN)*os per operand.
// M multiple of 128, K multiple of 32. N may be ragged (guarded).
#define LDS_ROW 36                  // 32 + 4 pad (floats)
#define TILEF   (128 * LDS_ROW)     // floats per tile buffer
#define BUF_F   (2 * TILEF)         // A + B
#define SMEM_BYTES (2 * BUF_F * 4)  // double-buffered

__device__ __forceinline__ void ldg_tile(float4* r, const float* src, int ld, int nrows,
                                         int k0, int t) {
#pragma unroll
    for (int i = 0; i < 4; i++) {
        int idx = t + i * 256;
        int row = idx >> 3;
        int kq  = idx & 7;
        if (row < nrows)
            r[i] = *(const float4*)(src + (long long)row * ld + k0 + kq * 4);
        else
            r[i] = make_float4(0.f, 0.f, 0.f, 0.f);
    }
}

__device__ __forceinline__ void sts_tile(float* dst, const float4* r, int t) {
#pragma unroll
    for (int i = 0; i < 4; i++) {
        int idx = t + i * 256;
        int row = idx >> 3;
        int kq  = idx & 7;
        float4 v;
        v.x = f2tf32f(r[i].x); v.y = f2tf32f(r[i].y);
        v.z = f2tf32f(r[i].z); v.w = f2tf32f(r[i].w);
        *(float4*)(dst + row * LDS_ROW + kq * 4) = v;
    }
}

__global__ void __launch_bounds__(256) gemm_mma(
    const float* __restrict__ A, const float* __restrict__ Bm, float* __restrict__ C,
    int M, int N, int K, int lda, int ldb, int ldc,
    long long isA, long long osA, long long isB, long long osB,
    long long isC, long long osC, int innerN,
    float alpha, int flags)
{
    extern __shared__ __align__(16) float smf[];
    int t = threadIdx.x;
    int wid = t >> 5, lane = t & 31;
    int wm = wid & 3;          // warp row  (4 along M): 32 rows each
    int wn = wid >> 2;         // warp col  (2 along N): 64 cols each
    int lr = lane >> 2, lc = lane & 3;

    int z = blockIdx.z;
    A  += (long long)(z % innerN) * isA + (long long)(z / innerN) * osA;
    Bm += (long long)(z % innerN) * isB + (long long)(z / innerN) * osB;
    C  += (long long)(z % innerN) * isC + (long long)(z / innerN) * osC;

    int m0 = blockIdx.y * 128;
    int n0 = blockIdx.x * 128;
    if ((flags & 1) && n0 > m0) return;
    int Keff = K;
    if (flags & 2) { int lim = m0 + 128; if (lim < Keff) Keff = lim; }
    int NK = Keff >> 5;

    const float* Abase = A + (long long)m0 * lda;
    const float* Bbase = Bm + (long long)n0 * ldb;
    int nvB = N - n0; if (nvB > 128) nvB = 128;

    float acc[2][8][4];
#pragma unroll
    for (int i = 0; i < 2; i++)
#pragma unroll
        for (int j = 0; j < 8; j++)
#pragma unroll
            for (int k = 0; k < 4; k++) acc[i][j][k] = 0.f;

    float4 pa[4], pb[4];
    // prologue: tile 0
    ldg_tile(pa, Abase, lda, 128, 0, t);
    ldg_tile(pb, Bbase, ldb, nvB, 0, t);
    sts_tile(smf, pa, t);
    sts_tile(smf + TILEF, pb, t);
    __syncthreads();

    for (int kt = 0; kt < NK; kt++) {
        int buf = kt & 1;
        if (kt + 1 < NK) {
            int k0 = (kt + 1) << 5;
            ldg_tile(pa, Abase, lda, 128, k0, t);
            ldg_tile(pb, Bbase, ldb, nvB, k0, t);
        }
        const float* As = smf + buf * BUF_F;
        const float* Bs = smf + buf * BUF_F + TILEF;
#pragma unroll
        for (int ks = 0; ks < 4; ks++) {
            int kk = ks * 8;
            float a[2][4];
#pragma unroll
            for (int mf = 0; mf < 2; mf++) {
                const float* ap = As + (wm * 32 + mf * 16 + lr) * LDS_ROW + kk + lc;
                a[mf][0] = ap[0];
                a[mf][1] = ap[8 * LDS_ROW];
                a[mf][2] = ap[4];
                a[mf][3] = ap[8 * LDS_ROW + 4];
            }
#pragma unroll
            for (int nf = 0; nf < 8; nf++) {
                const float* bp = Bs + (wn * 64 + nf * 8 + lr) * LDS_ROW + kk + lc;
                float b0 = bp[0];
                float b1 = bp[4];
                mma_tf32(acc[0][nf], a[0], b0, b1);
                mma_tf32(acc[1][nf], a[1], b0, b1);
            }
        }
        if (kt + 1 < NK) {
            int nb = (kt + 1) & 1;
            sts_tile(smf + nb * BUF_F, pa, t);
            sts_tile(smf + nb * BUF_F + TILEF, pb, t);
            __syncthreads();
        }
    }

    // epilogue: direct STG (pairs of consecutive columns per lane)
#pragma unroll
    for (int mf = 0; mf < 2; mf++) {
        int r0 = m0 + wm * 32 + mf * 16 + lr;
#pragma unroll
        for (int nf = 0; nf < 8; nf++) {
            int gn = n0 + wn * 64 + nf * 8 + 2 * lc;
            if (gn < N) {
                float2 v0 = make_float2(alpha * acc[mf][nf][0], alpha * acc[mf][nf][1]);
                float2 v1 = make_float2(alpha * acc[mf][nf][2], alpha * acc[mf][nf][3]);
                *(float2*)(C + (long long)r0 * ldc + gn) = v0;
                *(float2*)(C + (long long)(r0 + 8) * ldc + gn) = v1;
            }
        }
    }
}

// ---------------- RMSNorm ----------------
__global__ void rmsnorm_kernel(const float* __restrict__ in, const float* __restrict__ w,
                               float* __restrict__ out, int width, int in_stride, int out_stride)
{
    long long row = blockIdx.x;
    const float* x = in + row * in_stride;
    float* o = out + row * out_stride;
    __shared__ float red[256];
    int t = threadIdx.x;
    float ss = 0.f;
    for (int i = t; i < width; i += 256) { float v = x[i]; ss += v * v; }
    red[t] = ss;
    __syncthreads();
    for (int s = 128; s > 0; s >>= 1) {
        if (t < s) red[t] += red[t + s];
        __syncthreads();
    }
    float scale = rsqrtf(red[0] / (float)width + 1e-6f);
    for (int i = t; i < width; i += 256) o[i] = x[i] * scale * w[i];
}

// ---------------- RoPE + head assembly (V transposed) ----------------
__global__ void assemble_kernel(const float* __restrict__ q_full, const float* __restrict__ kv_a,
                                const float* __restrict__ kv_b, const float* __restrict__ freqs,
                                float* __restrict__ qh, float* __restrict__ kh, float* __restrict__ vhT)
{
    int bs = blockIdx.x;
    int h  = blockIdx.y;
    int s  = bs & (S_ - 1);
    int b  = bs >> 11;
    const float* fr  = freqs + (long long)s * D_ROPE;
    long long hd = ((long long)(b * H_ + h) * S_ + s);
    float* qo = qh + hd * D_QK;
    float* ko = kh + hd * D_QK;
    float* vo = vhT + ((long long)(b * H_ + h) * D_V) * S_;     // [d][s]
    const float* qi  = q_full + (long long)bs * (H_ * D_QK) + h * D_QK;
    const float* kvb = kv_b  + (long long)bs * (H_ * (D_NOPE + D_V)) + h * (D_NOPE + D_V);
    const float* kpe = kv_a  + (long long)bs * (KV_LORA + D_ROPE) + KV_LORA;

    int t = threadIdx.x;       // 128 threads
    qo[t] = qi[t];
    ko[t] = kvb[t];
    vo[(long long)t * S_ + s] = kvb[D_NOPE + t];
    if (t < 32) {
        float c  = fr[2 * t];
        float sn = fr[2 * t + 1];
        float x0 = qi[D_NOPE + 2 * t];
        float x1 = qi[D_NOPE + 2 * t + 1];
        qo[D_NOPE + 2 * t]     = x0 * c - x1 * sn;
        qo[D_NOPE + 2 * t + 1] = x0 * sn + x1 * c;
        float y0 = kpe[2 * t];
        float y1 = kpe[2 * t + 1];
        ko[D_NOPE + 2 * t]     = y0 * c - y1 * sn;
        ko[D_NOPE + 2 * t + 1] = y0 * sn + y1 * c;
    }
}

// ---------------- causal softmax (zeroes masked tail) ----------------
__global__ void softmax_kernel(float* __restrict__ scores)
{
    int q = blockIdx.x;
    long long bh = blockIdx.y;
    float* row = scores + (bh * S_ + q) * (long long)S_;
    int len = q + 1;
    __shared__ float red[256];
    int t = threadIdx.x;
    float v[8];
    float mx = -1e30f;
#pragma unroll
    for (int j = 0; j < 8; j++) {
        int i = t + j * 256;
        v[j] = (i < len) ? row[i] : -1e30f;
        mx = fmaxf(mx, v[j]);
    }
    red[t] = mx;
    __syncthreads();
    for (int s = 128; s > 0; s >>= 1) {
        if (t < s) red[t] = fmaxf(red[t], red[t + s]);
        __syncthreads();
    }
    mx = red[0];
    __syncthreads();
    float sum = 0.f;
#pragma unroll
    for (int j = 0; j < 8; j++) {
        v[j] = __expf(v[j] - mx);
        sum += v[j];
    }
    red[t] = sum;
    __syncthreads();
    for (int s = 128; s > 0; s >>= 1) {
        if (t < s) red[t] += red[t + s];
        __syncthreads();
    }
    float inv = 1.0f / red[0];
#pragma unroll
    for (int j = 0; j < 8; j++) {
        int i = t + j * 256;
        row[i] = (i < len) ? v[j] * inv : 0.0f;
    }
}

// ---------------- launch helper ----------------
static void launch_gemm(const float* A, const float* Bm, float* C,
                        int M, int N, int K, int lda, int ldb, int ldc,
                        long long isA, long long osA, long long isB, long long osB,
                        long long isC, long long osC, int innerN, int batches,
                        float alpha, int flags)
{
    dim3 grid((N + 127) / 128, (M + 127) / 128, batches);
    gemm_mma<<<grid, 256, SMEM_BYTES>>>(A, Bm, C, M, N, K, lda, ldb, ldc,
                                        isA, osA, isB, osB, isC, osC, innerN, alpha, flags);
}

extern "C" void kernel_launch(void* const* d_in, const int* in_sizes, int n_in,
                              void* d_out, int out_size)
{
    const float* x     = (const float*)d_in[0];
    const float* freqs = (const float*)d_in[1];
    const float* Wqa   = (const float*)d_in[2];
    const float* qlnw  = (const float*)d_in[3];
    const float* Wqb   = (const float*)d_in[4];
    const float* Wkva  = (const float*)d_in[5];
    const float* kvlnw = (const float*)d_in[6];
    const float* Wkvb  = (const float*)d_in[7];
    const float* Wo    = (const float*)d_in[8];
    float* out = (float*)d_out;

    cudaFuncSetAttribute(gemm_mma, cudaFuncAttributeMaxDynamicSharedMemorySize, SMEM_BYTES);

    float *qa, *qan, *qfull, *kva, *kvc, *kvb, *qh, *kh, *vhT, *scores, *attn;
    cudaGetSymbolAddress((void**)&qa,     g_qa);
    cudaGetSymbolAddress((void**)&qan,    g_qan);
    cudaGetSymbolAddress((void**)&qfull,  g_qfull);
    cudaGetSymbolAddress((void**)&kva,    g_kva);
    cudaGetSymbolAddress((void**)&kvc,    g_kvc);
    cudaGetSymbolAddress((void**)&kvb,    g_kvb);
    cudaGetSymbolAddress((void**)&qh,     g_qh);
    cudaGetSymbolAddress((void**)&kh,     g_kh);
    cudaGetSymbolAddress((void**)&vhT,    g_vhT);
    cudaGetSymbolAddress((void**)&scores, g_scores);
    cudaGetSymbolAddress((void**)&attn,   g_attn);

    const float SCALE = 1.0f / sqrtf((float)D_QK);
    const int CAUSAL = 1, KLIMIT = 2;

    // 1. q_a = x @ Wqa^T                   [4096,1536] K=2048
    launch_gemm(x, Wqa, qa, BS, Q_LORA, D_, D_, D_, Q_LORA,
                0, 0, 0, 0, 0, 0, 1, 1, 1.0f, 0);
    // 2. RMSNorm q_a
    rmsnorm_kernel<<<BS, 256>>>(qa, qlnw, qan, Q_LORA, Q_LORA, Q_LORA);
    // 3. q_full = q_a_n @ Wqb^T            [4096,3072] K=1536
    launch_gemm(qan, Wqb, qfull, BS, H_ * D_QK, Q_LORA, Q_LORA, Q_LORA, H_ * D_QK,
                0, 0, 0, 0, 0, 0, 1, 1, 1.0f, 0);
    // 4. kv_a = x @ Wkva^T                 [4096,576] K=2048 (ragged N)
    launch_gemm(x, Wkva, kva, BS, KV_LORA + D_ROPE, D_, D_, D_, KV_LORA + D_ROPE,
                0, 0, 0, 0, 0, 0, 1, 1, 1.0f, 0);
    // 5. RMSNorm kv_c
    rmsnorm_kernel<<<BS, 256>>>(kva, kvlnw, kvc, KV_LORA, KV_LORA + D_ROPE, KV_LORA);
    // 6. kv_b = kv_c @ Wkvb^T              [4096,4096] K=512
    launch_gemm(kvc, Wkvb, kvb, BS, H_ * (D_NOPE + D_V), KV_LORA, KV_LORA, KV_LORA, H_ * (D_NOPE + D_V),
                0, 0, 0, 0, 0, 0, 1, 1, 1.0f, 0);
    // 7. RoPE + assemble (V transposed to [b,h,d,s])
    assemble_kernel<<<dim3(BS, H_), 128>>>(qfull, kva, kvb, freqs, qh, kh, vhT);
    // 8. scores = SCALE * Q @ K^T, causal-skipped, batched over (b,h)
    {
        long long isQ = (long long)S_ * D_QK;
        long long isS = (long long)S_ * S_;
        launch_gemm(qh, kh, scores, S_, S_, D_QK, D_QK, D_QK, S_,
                    isQ, isQ * H_, isQ, isQ * H_, isS, isS * H_, H_, BH,
                    SCALE, CAUSAL);
    }
    // 9. causal softmax (+ zero masked tail)
    softmax_kernel<<<dim3(S_, BH), 256>>>(scores);
    // 10. attn = P @ V^T (NT via transposed V), K bounded per M-tile
    {
        long long isS = (long long)S_ * S_;
        long long isV = (long long)D_V * S_;
        launch_gemm(scores, vhT, attn, S_, D_V, S_, S_, S_, H_ * D_V,
                    isS, isS * H_, isV, isV * H_,
                    (long long)D_V, (long long)S_ * (H_ * D_V), H_, BH,
                    1.0f, KLIMIT);
    }
    // 11. out = attn @ Wo^T                [4096,2048] K=2048
    launch_gemm(attn, Wo, out, BS, D_, H_ * D_V, H_ * D_V, H_ * D_V, D_,
                0, 0, 0, 0, 0, 0, 1, 1, 1.0f, 0);
}

// round 8
// speedup vs baseline: 3.1255x; 1.2867x over previous
#include <cuda_runtime.h>
#include <cuda.h>
#include <cuda_bf16.h>
#include <math.h>
#include <cstdint>

// ---------------- problem constants ----------------
constexpr int B_ = 2;
constexpr int S_ = 2048;
constexpr int D_ = 2048;
constexpr int H_ = 16;
constexpr int Q_LORA = 1536;
constexpr int KV_LORA = 512;
constexpr int D_NOPE = 128;
constexpr int D_ROPE = 64;
constexpr int D_QK = D_NOPE + D_ROPE;   // 192
constexpr int D_V = 128;
constexpr int BS = B_ * S_;             // 4096
constexpr int BH = B_ * H_;             // 32

// ---------------- scratch (device globals) ----------------
__device__ float g_qa   [(size_t)BS * Q_LORA];
__device__ float g_qan  [(size_t)BS * Q_LORA];
__device__ float g_qfull[(size_t)BS * (H_ * D_QK)];
__device__ float g_kva  [(size_t)BS * (KV_LORA + D_ROPE)];
__device__ float g_kvc  [(size_t)BS * KV_LORA];
__device__ float g_kvb  [(size_t)BS * (H_ * (D_NOPE + D_V))];
__device__ float g_qh   [(size_t)BH * S_ * D_QK];
__device__ float g_kh   [(size_t)BH * S_ * D_QK];
__device__ float g_vhT  [(size_t)BH * D_V * S_];      // transposed: [b,h,d,s]
__device__ float g_scores[(size_t)BH * S_ * S_];
__device__ float g_attn [(size_t)BS * (H_ * D_V)];
// tf32-prerounded copies of inputs (cp.async path needs exact-tf32 sources)
__device__ float g_xr   [(size_t)BS * D_];
__device__ float g_wqar [(size_t)Q_LORA * D_];
__device__ float g_wqbr [(size_t)H_ * D_QK * Q_LORA];
__device__ float g_wkvar[(size_t)(KV_LORA + D_ROPE) * D_];
__device__ float g_wkvbr[(size_t)H_ * (D_NOPE + D_V) * KV_LORA];
__device__ float g_wor  [(size_t)D_ * H_ * D_V];

// ---------------- helpers ----------------
__device__ __forceinline__ float f2tf32f(float f) {
    uint32_t r;
    asm("cvt.rna.tf32.f32 %0, %1;" : "=r"(r) : "f"(f));
    return __uint_as_float(r);
}

__device__ __forceinline__ void mma_tf32(float* c, const float* a, float b0, float b1) {
    asm volatile(
        "mma.sync.aligned.m16n8k8.row.col.f32.tf32.tf32.f32 "
        "{%0,%1,%2,%3}, {%4,%5,%6,%7}, {%8,%9}, {%0,%1,%2,%3};"
        : "+f"(c[0]), "+f"(c[1]), "+f"(c[2]), "+f"(c[3])
        : "r"(__float_as_uint(a[0])), "r"(__float_as_uint(a[1])),
          "r"(__float_as_uint(a[2])), "r"(__float_as_uint(a[3])),
          "r"(__float_as_uint(b0)), "r"(__float_as_uint(b1)));
}

__device__ __forceinline__ void cp16(uint32_t dst, const float* src, int bytes) {
    asm volatile("cp.async.cg.shared.global [%0], [%1], 16, %2;"
                 :: "r"(dst), "l"(src), "r"(bytes));
}
#define CP_COMMIT() asm volatile("cp.async.commit_group;" ::: "memory")
#define CP_WAIT(n)  asm volatile("cp.async.wait_group %0;" :: "n"(n) : "memory")

// ---------------- tf32 mma.sync GEMM, cp.async 3-stage ----------------
// C[M,N] = alpha * A[M,K] * B[N,K]^T   (both K-major, NT)
// flags bit0: causal tile skip. bit1: Keff=min(K,m0+128). bit3: round output to tf32.
// ALL inputs must already be tf32-exact (pre-rounded); HW truncation is then lossless.
// M mult of 128, K mult of 32, N ragged (guarded).
#define STAGES  3
#define TILE_F  4096                    // 128 rows x 32 floats
#define STAGE_F (2 * TILE_F)            // A + B
#define SMEM_BYTES (STAGES * STAGE_F * 4)   // 98304

__global__ void __launch_bounds__(256, 2) gemm_mma(
    const float* __restrict__ A, const float* __restrict__ Bm, float* __restrict__ C,
    int M, int N, int K, int lda, int ldb, int ldc,
    long long isA, long long osA, long long isB, long long osB,
    long long isC, long long osC, int innerN,
    float alpha, int flags)
{
    extern __shared__ __align__(16) float smf[];
    int t = threadIdx.x;
    int wid = t >> 5, lane = t & 31;
    int wm = wid & 3;          // 4 warps along M (32 rows each)
    int wn = wid >> 2;         // 2 warps along N (64 cols each)
    int lr = lane >> 2, lc = lane & 3;

    int z = blockIdx.z;
    A  += (long long)(z % innerN) * isA + (long long)(z / innerN) * osA;
    Bm += (long long)(z % innerN) * isB + (long long)(z / innerN) * osB;
    C  += (long long)(z % innerN) * isC + (long long)(z / innerN) * osC;

    int m0 = blockIdx.y * 128;
    int n0 = blockIdx.x * 128;
    if ((flags & 1) && n0 > m0) return;
    int Keff = K;
    if (flags & 2) { int lim = m0 + 128; if (lim < Keff) Keff = lim; }
    int NK = Keff >> 5;

    const float* Abase = A + (long long)m0 * lda;
    const float* Bbase = Bm + (long long)n0 * ldb;
    int nvB = N - n0; if (nvB > 128) nvB = 128;

    uint32_t sb = (uint32_t)__cvta_generic_to_shared(smf);

    // per-thread cp.async coords: 4 float4 per operand tile
    int crow[4], ckq[4], cq4[4];
#pragma unroll
    for (int i = 0; i < 4; i++) {
        int idx = t + i * 256;
        crow[i] = idx >> 3;
        ckq[i]  = idx & 7;
        cq4[i]  = (ckq[i] ^ (crow[i] & 7)) << 2;   // swizzled quad -> float offset
    }

    auto issue = [&](int stage, int k0) {
        uint32_t dA = sb + (uint32_t)(stage * STAGE_F) * 4u;
        uint32_t dB = dA + TILE_F * 4u;
#pragma unroll
        for (int i = 0; i < 4; i++) {
            int row = crow[i];
            cp16(dA + (uint32_t)(row * 32 + cq4[i]) * 4u,
                 Abase + (long long)row * lda + k0 + ckq[i] * 4, 16);
            int brow = (row < nvB) ? row : 0;
            cp16(dB + (uint32_t)(row * 32 + cq4[i]) * 4u,
                 Bbase + (long long)brow * ldb + k0 + ckq[i] * 4,
                 (row < nvB) ? 16 : 0);
        }
    };

    float acc[2][8][4];
#pragma unroll
    for (int i = 0; i < 2; i++)
#pragma unroll
        for (int j = 0; j < 8; j++)
#pragma unroll
            for (int k = 0; k < 4; k++) acc[i][j][k] = 0.f;

    // prologue: stages 0,1
    issue(0, 0); CP_COMMIT();
    if (NK > 1) issue(1, 32);
    CP_COMMIT();
    int fetch = 2;

    for (int kt = 0; kt < NK; kt++) {
        CP_WAIT(1);
        __syncthreads();
        if (fetch < NK) issue(fetch % STAGES, fetch << 5);
        CP_COMMIT();
        fetch++;

        const float* As = smf + (kt % STAGES) * STAGE_F;
        const float* Bs = As + TILE_F;
#pragma unroll
        for (int ks = 0; ks < 4; ks++) {
            int kq = ks * 2;
            int p0 = ((kq ^ lr) << 2) + lc;
            int p1 = (((kq | 1) ^ lr) << 2) + lc;
            float a[2][4];
#pragma unroll
            for (int mf = 0; mf < 2; mf++) {
                const float* ap = As + (wm * 32 + mf * 16 + lr) * 32;
                a[mf][0] = ap[p0];
                a[mf][1] = ap[8 * 32 + p0];
                a[mf][2] = ap[p1];
                a[mf][3] = ap[8 * 32 + p1];
            }
#pragma unroll
            for (int nf = 0; nf < 8; nf++) {
                const float* bp = Bs + (wn * 64 + nf * 8 + lr) * 32;
                float b0 = bp[p0];
                float b1 = bp[p1];
                mma_tf32(acc[0][nf], a[0], b0, b1);
                mma_tf32(acc[1][nf], a[1], b0, b1);
            }
        }
    }

    // epilogue: direct STG (optionally tf32-round for downstream GEMM consumption)
    bool rnd = (flags & 8) != 0;
#pragma unroll
    for (int mf = 0; mf < 2; mf++) {
        int r0 = m0 + wm * 32 + mf * 16 + lr;
#pragma unroll
        for (int nf = 0; nf < 8; nf++) {
            int gn = n0 + wn * 64 + nf * 8 + 2 * lc;
            if (gn < N) {
                float v0 = alpha * acc[mf][nf][0], v1 = alpha * acc[mf][nf][1];
                float v2 = alpha * acc[mf][nf][2], v3 = alpha * acc[mf][nf][3];
                if (rnd) { v0 = f2tf32f(v0); v1 = f2tf32f(v1); v2 = f2tf32f(v2); v3 = f2tf32f(v3); }
                *(float2*)(C + (long long)r0 * ldc + gn) = make_float2(v0, v1);
                *(float2*)(C + (long long)(r0 + 8) * ldc + gn) = make_float2(v2, v3);
            }
        }
    }
}

// ---------------- tf32 pre-round convert (float4 grid-stride) ----------------
__global__ void cvt_tf32_kernel(const float* __restrict__ in, float* __restrict__ out, int n4)
{
    int i = blockIdx.x * blockDim.x + threadIdx.x;
    int stride = gridDim.x * blockDim.x;
    for (; i < n4; i += stride) {
        float4 v = ((const float4*)in)[i];
        v.x = f2tf32f(v.x); v.y = f2tf32f(v.y);
        v.z = f2tf32f(v.z); v.w = f2tf32f(v.w);
        ((float4*)out)[i] = v;
    }
}

// ---------------- RMSNorm (tf32-rounded output) ----------------
__global__ void rmsnorm_kernel(const float* __restrict__ in, const float* __restrict__ w,
                               float* __restrict__ out, int width, int in_stride, int out_stride)
{
    long long row = blockIdx.x;
    const float* x = in + row * in_stride;
    float* o = out + row * out_stride;
    __shared__ float red[256];
    int t = threadIdx.x;
    float ss = 0.f;
    for (int i = t; i < width; i += 256) { float v = x[i]; ss += v * v; }
    red[t] = ss;
    __syncthreads();
    for (int s = 128; s > 0; s >>= 1) {
        if (t < s) red[t] += red[t + s];
        __syncthreads();
    }
    float scale = rsqrtf(red[0] / (float)width + 1e-6f);
    for (int i = t; i < width; i += 256) o[i] = f2tf32f(x[i] * scale * w[i]);
}

// ---------------- RoPE + head assembly (tf32-rounded, V transposed) ----------------
__global__ void assemble_kernel(const float* __restrict__ q_full, const float* __restrict__ kv_a,
                                const float* __restrict__ kv_b, const float* __restrict__ freqs,
                                float* __restrict__ qh, float* __restrict__ kh, float* __restrict__ vhT)
{
    int bs = blockIdx.x;
    int h  = blockIdx.y;
    int s  = bs & (S_ - 1);
    int b  = bs >> 11;
    const float* fr  = freqs + (long long)s * D_ROPE;
    long long hd = ((long long)(b * H_ + h) * S_ + s);
    float* qo = qh + hd * D_QK;
    float* ko = kh + hd * D_QK;
    float* vo = vhT + ((long long)(b * H_ + h) * D_V) * S_;     // [d][s]
    const float* qi  = q_full + (long long)bs * (H_ * D_QK) + h * D_QK;
    const float* kvb = kv_b  + (long long)bs * (H_ * (D_NOPE + D_V)) + h * (D_NOPE + D_V);
    const float* kpe = kv_a  + (long long)bs * (KV_LORA + D_ROPE) + KV_LORA;

    int t = threadIdx.x;       // 128 threads
    qo[t] = f2tf32f(qi[t]);
    ko[t] = f2tf32f(kvb[t]);
    vo[(long long)t * S_ + s] = f2tf32f(kvb[D_NOPE + t]);
    if (t < 32) {
        float c  = fr[2 * t];
        float sn = fr[2 * t + 1];
        float x0 = qi[D_NOPE + 2 * t];
        float x1 = qi[D_NOPE + 2 * t + 1];
        qo[D_NOPE + 2 * t]     = f2tf32f(x0 * c - x1 * sn);
        qo[D_NOPE + 2 * t + 1] = f2tf32f(x0 * sn + x1 * c);
        float y0 = kpe[2 * t];
        float y1 = kpe[2 * t + 1];
        ko[D_NOPE + 2 * t]     = f2tf32f(y0 * c - y1 * sn);
        ko[D_NOPE + 2 * t + 1] = f2tf32f(y0 * sn + y1 * c);
    }
}

// ---------------- causal softmax (zeroes masked tail, tf32-rounded output) ----------------
__global__ void softmax_kernel(float* __restrict__ scores)
{
    int q = blockIdx.x;
    long long bh = blockIdx.y;
    float* row = scores + (bh * S_ + q) * (long long)S_;
    int len = q + 1;
    __shared__ float red[256];
    int t = threadIdx.x;
    float v[8];
    float mx = -1e30f;
#pragma unroll
    for (int j = 0; j < 8; j++) {
        int i = t + j * 256;
        v[j] = (i < len) ? row[i] : -1e30f;
        mx = fmaxf(mx, v[j]);
    }
    red[t] = mx;
    __syncthreads();
    for (int s = 128; s > 0; s >>= 1) {
        if (t < s) red[t] = fmaxf(red[t], red[t + s]);
        __syncthreads();
    }
    mx = red[0];
    __syncthreads();
    float sum = 0.f;
#pragma unroll
    for (int j = 0; j < 8; j++) {
        v[j] = __expf(v[j] - mx);
        sum += v[j];
    }
    red[t] = sum;
    __syncthreads();
    for (int s = 128; s > 0; s >>= 1) {
        if (t < s) red[t] += red[t + s];
        __syncthreads();
    }
    float inv = 1.0f / red[0];
#pragma unroll
    for (int j = 0; j < 8; j++) {
        int i = t + j * 256;
        row[i] = (i < len) ? f2tf32f(v[j] * inv) : 0.0f;
    }
}

// ---------------- launch helper ----------------
static void launch_gemm(const float* A, const float* Bm, float* C,
                        int M, int N, int K, int lda, int ldb, int ldc,
                        long long isA, long long osA, long long isB, long long osB,
                        long long isC, long long osC, int innerN, int batches,
                        float alpha, int flags)
{
    dim3 grid((N + 127) / 128, (M + 127) / 128, batches);
    gemm_mma<<<grid, 256, SMEM_BYTES>>>(A, Bm, C, M, N, K, lda, ldb, ldc,
                                        isA, osA, isB, osB, isC, osC, innerN, alpha, flags);
}

static void launch_cvt(const float* in, float* out, size_t n)
{
    int n4 = (int)(n / 4);
    int blocks = (n4 + 255) / 256;
    if (blocks > 8192) blocks = 8192;
    cvt_tf32_kernel<<<blocks, 256>>>(in, out, n4);
}

extern "C" void kernel_launch(void* const* d_in, const int* in_sizes, int n_in,
                              void* d_out, int out_size)
{
    const float* x     = (const float*)d_in[0];
    const float* freqs = (const float*)d_in[1];
    const float* Wqa   = (const float*)d_in[2];
    const float* qlnw  = (const float*)d_in[3];
    const float* Wqb   = (const float*)d_in[4];
    const float* Wkva  = (const float*)d_in[5];
    const float* kvlnw = (const float*)d_in[6];
    const float* Wkvb  = (const float*)d_in[7];
    const float* Wo    = (const float*)d_in[8];
    float* out = (float*)d_out;

    cudaFuncSetAttribute(gemm_mma, cudaFuncAttributeMaxDynamicSharedMemorySize, SMEM_BYTES);

    float *qa, *qan, *qfull, *kva, *kvc, *kvb, *qh, *kh, *vhT, *scores, *attn;
    float *xr, *wqar, *wqbr, *wkvar, *wkvbr, *wor;
    cudaGetSymbolAddress((void**)&qa,     g_qa);
    cudaGetSymbolAddress((void**)&qan,    g_qan);
    cudaGetSymbolAddress((void**)&qfull,  g_qfull);
    cudaGetSymbolAddress((void**)&kva,    g_kva);
    cudaGetSymbolAddress((void**)&kvc,    g_kvc);
    cudaGetSymbolAddress((void**)&kvb,    g_kvb);
    cudaGetSymbolAddress((void**)&qh,     g_qh);
    cudaGetSymbolAddress((void**)&kh,     g_kh);
    cudaGetSymbolAddress((void**)&vhT,    g_vhT);
    cudaGetSymbolAddress((void**)&scores, g_scores);
    cudaGetSymbolAddress((void**)&attn,   g_attn);
    cudaGetSymbolAddress((void**)&xr,     g_xr);
    cudaGetSymbolAddress((void**)&wqar,   g_wqar);
    cudaGetSymbolAddress((void**)&wqbr,   g_wqbr);
    cudaGetSymbolAddress((void**)&wkvar,  g_wkvar);
    cudaGetSymbolAddress((void**)&wkvbr,  g_wkvbr);
    cudaGetSymbolAddress((void**)&wor,    g_wor);

    const float SCALE = 1.0f / sqrtf((float)D_QK);
    const int CAUSAL = 1, KLIMIT = 2, ROUND = 8;

    // 0. pre-round all external GEMM inputs to tf32 (RNA)
    launch_cvt(x,    xr,    (size_t)BS * D_);
    launch_cvt(Wqa,  wqar,  (size_t)Q_LORA * D_);
    launch_cvt(Wqb,  wqbr,  (size_t)H_ * D_QK * Q_LORA);
    launch_cvt(Wkva, wkvar, (size_t)(KV_LORA + D_ROPE) * D_);
    launch_cvt(Wkvb, wkvbr, (size_t)H_ * (D_NOPE + D_V) * KV_LORA);
    launch_cvt(Wo,   wor,   (size_t)D_ * H_ * D_V);

    // 1. q_a = x @ Wqa^T                   [4096,1536] K=2048
    launch_gemm(xr, wqar, qa, BS, Q_LORA, D_, D_, D_, Q_LORA,
                0, 0, 0, 0, 0, 0, 1, 1, 1.0f, 0);
    // 2. RMSNorm q_a (rounds)
    rmsnorm_kernel<<<BS, 256>>>(qa, qlnw, qan, Q_LORA, Q_LORA, Q_LORA);
    // 3. q_full = q_a_n @ Wqb^T            [4096,3072] K=1536
    launch_gemm(qan, wqbr, qfull, BS, H_ * D_QK, Q_LORA, Q_LORA, Q_LORA, H_ * D_QK,
                0, 0, 0, 0, 0, 0, 1, 1, 1.0f, 0);
    // 4. kv_a = x @ Wkva^T                 [4096,576] K=2048 (ragged N)
    launch_gemm(xr, wkvar, kva, BS, KV_LORA + D_ROPE, D_, D_, D_, KV_LORA + D_ROPE,
                0, 0, 0, 0, 0, 0, 1, 1, 1.0f, 0);
    // 5. RMSNorm kv_c (rounds)
    rmsnorm_kernel<<<BS, 256>>>(kva, kvlnw, kvc, KV_LORA, KV_LORA + D_ROPE, KV_LORA);
    // 6. kv_b = kv_c @ Wkvb^T              [4096,4096] K=512
    launch_gemm(kvc, wkvbr, kvb, BS, H_ * (D_NOPE + D_V), KV_LORA, KV_LORA, KV_LORA, H_ * (D_NOPE + D_V),
                0, 0, 0, 0, 0, 0, 1, 1, 1.0f, 0);
    // 7. RoPE + assemble (rounds; V transposed to [b,h,d,s])
    assemble_kernel<<<dim3(BS, H_), 128>>>(qfull, kva, kvb, freqs, qh, kh, vhT);
    // 8. scores = SCALE * Q @ K^T, causal-skipped, batched over (b,h)
    {
        long long isQ = (long long)S_ * D_QK;
        long long isS = (long long)S_ * S_;
        launch_gemm(qh, kh, scores, S_, S_, D_QK, D_QK, D_QK, S_,
                    isQ, isQ * H_, isQ, isQ * H_, isS, isS * H_, H_, BH,
                    SCALE, CAUSAL);
    }
    // 9. causal softmax (rounds + zeroes masked tail)
    softmax_kernel<<<dim3(S_, BH), 256>>>(scores);
    // 10. attn = P @ V^T (NT via transposed V), K bounded per M-tile; round for GEMM 11
    {
        long long isS = (long long)S_ * S_;
        long long isV = (long long)D_V * S_;
        launch_gemm(scores, vhT, attn, S_, D_V, S_, S_, S_, H_ * D_V,
                    isS, isS * H_, isV, isV * H_,
                    (long long)D_V, (long long)S_ * (H_ * D_V), H_, BH,
                    1.0f, KLIMIT | ROUND);
    }
    // 11. out = attn @ Wo^T                [4096,2048] K=2048
    launch_gemm(attn, wor, out, BS, D_, H_ * D_V, H_ * D_V, H_ * D_V, D_,
                0, 0, 0, 0, 0, 0, 1, 1, 1.0f, 0);
}

// round 9
// speedup vs baseline: 5.7311x; 1.8336x over previous
#include <cuda_runtime.h>
#include <cuda.h>
#include <cuda_fp16.h>
#include <math.h>
#include <cstdint>

// ---------------- problem constants ----------------
constexpr int B_ = 2;
constexpr int S_ = 2048;
constexpr int D_ = 2048;
constexpr int H_ = 16;
constexpr int Q_LORA = 1536;
constexpr int KV_LORA = 512;
constexpr int D_NOPE = 128;
constexpr int D_ROPE = 64;
constexpr int D_QK = D_NOPE + D_ROPE;   // 192
constexpr int D_V = 128;
constexpr int BS = B_ * S_;             // 4096
constexpr int BH = B_ * H_;             // 32

// ---------------- scratch (device globals) ----------------
// fp32 intermediates (pre-norm / scores)
__device__ float  g_qa   [(size_t)BS * Q_LORA];
__device__ float  g_kva  [(size_t)BS * (KV_LORA + D_ROPE)];
__device__ float  g_scores[(size_t)BH * S_ * S_];
// fp16 GEMM operands
__device__ __half g_xh   [(size_t)BS * D_];
__device__ __half g_wqah [(size_t)Q_LORA * D_];
__device__ __half g_wqbh [(size_t)H_ * D_QK * Q_LORA];
__device__ __half g_wkvah[(size_t)(KV_LORA + D_ROPE) * D_];
__device__ __half g_wkvbh[(size_t)H_ * (D_NOPE + D_V) * KV_LORA];
__device__ __half g_woh  [(size_t)D_ * H_ * D_V];
__device__ __half g_qan  [(size_t)BS * Q_LORA];
__device__ __half g_kvc  [(size_t)BS * KV_LORA];
__device__ __half g_qfull[(size_t)BS * (H_ * D_QK)];
__device__ __half g_kvb  [(size_t)BS * (H_ * (D_NOPE + D_V))];
__device__ __half g_qh   [(size_t)BH * S_ * D_QK];
__device__ __half g_kh   [(size_t)BH * S_ * D_QK];
__device__ __half g_vhT  [(size_t)BH * D_V * S_];     // transposed: [b,h,d,s]
__device__ __half g_probs[(size_t)BH * S_ * S_];
__device__ __half g_attn [(size_t)BS * (H_ * D_V)];

// ---------------- PTX helpers ----------------
__device__ __forceinline__ void mma_f16(float* c, const uint32_t* a, uint32_t b0, uint32_t b1) {
    asm volatile(
        "mma.sync.aligned.m16n8k16.row.col.f32.f16.f16.f32 "
        "{%0,%1,%2,%3}, {%4,%5,%6,%7}, {%8,%9}, {%0,%1,%2,%3};"
        : "+f"(c[0]), "+f"(c[1]), "+f"(c[2]), "+f"(c[3])
        : "r"(a[0]), "r"(a[1]), "r"(a[2]), "r"(a[3]), "r"(b0), "r"(b1));
}
__device__ __forceinline__ void ldsm4(uint32_t* r, uint32_t addr) {
    asm volatile("ldmatrix.sync.aligned.m8n8.x4.shared.b16 {%0,%1,%2,%3}, [%4];"
                 : "=r"(r[0]), "=r"(r[1]), "=r"(r[2]), "=r"(r[3]) : "r"(addr));
}
__device__ __forceinline__ void cp16(uint32_t dst, const void* src, int bytes) {
    asm volatile("cp.async.cg.shared.global [%0], [%1], 16, %2;"
                 :: "r"(dst), "l"(src), "r"(bytes));
}
#define CP_COMMIT() asm volatile("cp.async.commit_group;" ::: "memory")
#define CP_WAIT(n)  asm volatile("cp.async.wait_group %0;" :: "n"(n) : "memory")

// ---------------- fp16 mma.sync GEMM, cp.async 3-stage ----------------
// C[M,N] = alpha * A[M,K] * B[N,K]^T   (half operands, K-major NT, fp32 accum)
// flags bit0: causal tile skip. bit1: Keff=min(K,m0+128). bit2: C is __half.
// M mult of 128, K mult of 64, N ragged (guarded). Tiles: 128x128xK64.
#define STAGES   3
#define TILE_B   16384                    // 128 rows x 128 bytes (64 halfs)
#define STAGE_B  (2 * TILE_B)             // A + B
#define SMEM_BYTES (STAGES * STAGE_B)     // 98304

__global__ void __launch_bounds__(256, 2) gemm_h(
    const __half* __restrict__ A, const __half* __restrict__ Bm, void* __restrict__ Cv,
    int M, int N, int K, int lda, int ldb, int ldc,
    long long isA, long long osA, long long isB, long long osB,
    long long isC, long long osC, int innerN,
    float alpha, int flags)
{
    extern __shared__ __align__(16) char smc[];
    int t = threadIdx.x;
    int wid = t >> 5, lane = t & 31;
    int wm = wid & 3;          // 4 warps along M (32 rows each)
    int wn = wid >> 2;         // 2 warps along N (64 cols each)
    int lr = lane >> 2, lc = lane & 3;

    int z = blockIdx.z;
    A  += (long long)(z % innerN) * isA + (long long)(z / innerN) * osA;
    Bm += (long long)(z % innerN) * isB + (long long)(z / innerN) * osB;
    long long coff = (long long)(z % innerN) * isC + (long long)(z / innerN) * osC;

    int m0 = blockIdx.y * 128;
    int n0 = blockIdx.x * 128;
    if ((flags & 1) && n0 > m0) return;
    int Keff = K;
    if (flags & 2) { int lim = m0 + 128; if (lim < Keff) Keff = lim; }
    int NK = Keff >> 6;

    const __half* Abase = A + (long long)m0 * lda;
    const __half* Bbase = Bm + (long long)n0 * ldb;
    int nvB = N - n0; if (nvB > 128) nvB = 128;

    uint32_t sb = (uint32_t)__cvta_generic_to_shared(smc);

    // cp.async coords: 4 x 16B chunks per operand tile per thread
    int crow[4], ckc[4];
    uint32_t cdst[4];
#pragma unroll
    for (int i = 0; i < 4; i++) {
        int idx = t + i * 256;
        crow[i] = idx >> 3;
        ckc[i]  = idx & 7;
        cdst[i] = (uint32_t)(crow[i] * 128 + ((ckc[i] ^ (crow[i] & 7)) << 4));
    }

    auto issue = [&](int stage, int k0) {
        uint32_t dA = sb + (uint32_t)(stage * STAGE_B);
        uint32_t dB = dA + TILE_B;
#pragma unroll
        for (int i = 0; i < 4; i++) {
            int row = crow[i];
            cp16(dA + cdst[i], Abase + (long long)row * lda + k0 + ckc[i] * 8, 16);
            int brow = (row < nvB) ? row : 0;
            cp16(dB + cdst[i], Bbase + (long long)brow * ldb + k0 + ckc[i] * 8,
                 (row < nvB) ? 16 : 0);
        }
    };

    // ldmatrix per-thread bases
    int aRow0 = wm * 32 + (lane & 15);          // + mf*16
    int aSel  = (lane >> 4) & 1;
    int bRow0 = wn * 64 + (lane & 7) + (((lane >> 4) & 1) << 3);   // + nf2*16
    int bSel  = (lane >> 3) & 1;

    float acc[2][8][4];
#pragma unroll
    for (int i = 0; i < 2; i++)
#pragma unroll
        for (int j = 0; j < 8; j++)
#pragma unroll
            for (int k = 0; k < 4; k++) acc[i][j][k] = 0.f;

    issue(0, 0); CP_COMMIT();
    if (NK > 1) issue(1, 64);
    CP_COMMIT();
    int fetch = 2;

    for (int kt = 0; kt < NK; kt++) {
        CP_WAIT(1);
        __syncthreads();
        if (fetch < NK) issue(fetch % STAGES, fetch << 6);
        CP_COMMIT();
        fetch++;

        uint32_t sA = sb + (uint32_t)((kt % STAGES) * STAGE_B);
        uint32_t sB = sA + TILE_B;
#pragma unroll
        for (int ks = 0; ks < 4; ks++) {
            uint32_t a[2][4];
#pragma unroll
            for (int mf = 0; mf < 2; mf++) {
                int row = aRow0 + mf * 16;
                uint32_t addr = sA + row * 128 + ((((ks << 1) | aSel) ^ (row & 7)) << 4);
                ldsm4(a[mf], addr);
            }
#pragma unroll
            for (int nf2 = 0; nf2 < 4; nf2++) {
                int row = bRow0 + nf2 * 16;
                uint32_t addr = sB + row * 128 + ((((ks << 1) | bSel) ^ (row & 7)) << 4);
                uint32_t b[4];
                ldsm4(b, addr);
                mma_f16(acc[0][2 * nf2],     a[0], b[0], b[1]);
                mma_f16(acc[1][2 * nf2],     a[1], b[0], b[1]);
                mma_f16(acc[0][2 * nf2 + 1], a[0], b[2], b[3]);
                mma_f16(acc[1][2 * nf2 + 1], a[1], b[2], b[3]);
            }
        }
    }

    // epilogue
    bool hout = (flags & 4) != 0;
#pragma unroll
    for (int mf = 0; mf < 2; mf++) {
        int r0 = m0 + wm * 32 + mf * 16 + lr;
#pragma unroll
        for (int nf = 0; nf < 8; nf++) {
            int gn = n0 + wn * 64 + nf * 8 + 2 * lc;
            if (gn < N) {
                float v0 = alpha * acc[mf][nf][0], v1 = alpha * acc[mf][nf][1];
                float v2 = alpha * acc[mf][nf][2], v3 = alpha * acc[mf][nf][3];
                if (hout) {
                    __half* C = (__half*)Cv + coff;
                    *(__half2*)(C + (long long)r0 * ldc + gn) = __floats2half2_rn(v0, v1);
                    *(__half2*)(C + (long long)(r0 + 8) * ldc + gn) = __floats2half2_rn(v2, v3);
                } else {
                    float* C = (float*)Cv + coff;
                    *(float2*)(C + (long long)r0 * ldc + gn) = make_float2(v0, v1);
                    *(float2*)(C + (long long)(r0 + 8) * ldc + gn) = make_float2(v2, v3);
                }
            }
        }
    }
}

// ---------------- fp32 -> fp16 convert ----------------
__global__ void cvt_f2h_kernel(const float* __restrict__ in, __half* __restrict__ out, int n4)
{
    int i = blockIdx.x * blockDim.x + threadIdx.x;
    int stride = gridDim.x * blockDim.x;
    for (; i < n4; i += stride) {
        float4 v = ((const float4*)in)[i];
        __half2 h0 = __floats2half2_rn(v.x, v.y);
        __half2 h1 = __floats2half2_rn(v.z, v.w);
        *(uint2*)(out + (size_t)i * 4) = make_uint2(
            *(uint32_t*)&h0, *(uint32_t*)&h1);
    }
}

// ---------------- RMSNorm (fp32 in, fp16 out) ----------------
__global__ void rmsnorm_kernel(const float* __restrict__ in, const float* __restrict__ w,
                               __half* __restrict__ out, int width, int in_stride, int out_stride)
{
    long long row = blockIdx.x;
    const float* x = in + row * in_stride;
    __half* o = out + row * out_stride;
    __shared__ float red[256];
    int t = threadIdx.x;
    float ss = 0.f;
    for (int i = t; i < width; i += 256) { float v = x[i]; ss += v * v; }
    red[t] = ss;
    __syncthreads();
    for (int s = 128; s > 0; s >>= 1) {
        if (t < s) red[t] += red[t + s];
        __syncthreads();
    }
    float scale = rsqrtf(red[0] / (float)width + 1e-6f);
    for (int i = t; i < width; i += 256) o[i] = __float2half_rn(x[i] * scale * w[i]);
}

// ---------------- RoPE + head assembly (fp16 out, V transposed) ----------------
__global__ void assemble_kernel(const __half* __restrict__ q_full, const float* __restrict__ kv_a,
                                const __half* __restrict__ kv_b, const float* __restrict__ freqs,
                                __half* __restrict__ qh, __half* __restrict__ kh,
                                __half* __restrict__ vhT)
{
    int bs = blockIdx.x;
    int h  = blockIdx.y;
    int s  = bs & (S_ - 1);
    int b  = bs >> 11;
    const float* fr = freqs + (long long)s * D_ROPE;
    long long hd = ((long long)(b * H_ + h) * S_ + s);
    __half* qo = qh + hd * D_QK;
    __half* ko = kh + hd * D_QK;
    __half* vo = vhT + ((long long)(b * H_ + h) * D_V) * S_;     // [d][s]
    const __half* qi  = q_full + (long long)bs * (H_ * D_QK) + h * D_QK;
    const __half* kvb = kv_b  + (long long)bs * (H_ * (D_NOPE + D_V)) + h * (D_NOPE + D_V);
    const float* kpe  = kv_a  + (long long)bs * (KV_LORA + D_ROPE) + KV_LORA;

    int t = threadIdx.x;       // 128 threads
    qo[t] = qi[t];
    ko[t] = kvb[t];
    vo[(long long)t * S_ + s] = kvb[D_NOPE + t];
    if (t < 32) {
        float c  = fr[2 * t];
        float sn = fr[2 * t + 1];
        float x0 = __half2float(qi[D_NOPE + 2 * t]);
        float x1 = __half2float(qi[D_NOPE + 2 * t + 1]);
        qo[D_NOPE + 2 * t]     = __float2half_rn(x0 * c - x1 * sn);
        qo[D_NOPE + 2 * t + 1] = __float2half_rn(x0 * sn + x1 * c);
        float y0 = kpe[2 * t];
        float y1 = kpe[2 * t + 1];
        ko[D_NOPE + 2 * t]     = __float2half_rn(y0 * c - y1 * sn);
        ko[D_NOPE + 2 * t + 1] = __float2half_rn(y0 * sn + y1 * c);
    }
}

// ---------------- causal softmax (fp32 scores -> fp16 probs, zero tail) ----------------
__global__ void softmax_kernel(const float* __restrict__ scores, __half* __restrict__ probs)
{
    int q = blockIdx.x;
    long long bh = blockIdx.y;
    const float* row = scores + (bh * S_ + q) * (long long)S_;
    __half* prow = probs + (bh * S_ + q) * (long long)S_;
    int len = q + 1;
    __shared__ float red[256];
    int t = threadIdx.x;
    float v[8];
    float mx = -1e30f;
#pragma unroll
    for (int j = 0; j < 8; j++) {
        int i = t + j * 256;
        v[j] = (i < len) ? row[i] : -1e30f;
        mx = fmaxf(mx, v[j]);
    }
    red[t] = mx;
    __syncthreads();
    for (int s = 128; s > 0; s >>= 1) {
        if (t < s) red[t] = fmaxf(red[t], red[t + s]);
        __syncthreads();
    }
    mx = red[0];
    __syncthreads();
    float sum = 0.f;
#pragma unroll
    for (int j = 0; j < 8; j++) {
        v[j] = __expf(v[j] - mx);
        sum += v[j];
    }
    red[t] = sum;
    __syncthreads();
    for (int s = 128; s > 0; s >>= 1) {
        if (t < s) red[t] += red[t + s];
        __syncthreads();
    }
    float inv = 1.0f / red[0];
#pragma unroll
    for (int j = 0; j < 8; j++) {
        int i = t + j * 256;
        prow[i] = (i < len) ? __float2half_rn(v[j] * inv) : __half(0.0f);
    }
}

// ---------------- launch helpers ----------------
static void launch_gemm(const __half* A, const __half* Bm, void* C,
                        int M, int N, int K, int lda, int ldb, int ldc,
                        long long isA, long long osA, long long isB, long long osB,
                        long long isC, long long osC, int innerN, int batches,
                        float alpha, int flags)
{
    dim3 grid((N + 127) / 128, (M + 127) / 128, batches);
    gemm_h<<<grid, 256, SMEM_BYTES>>>(A, Bm, C, M, N, K, lda, ldb, ldc,
                                      isA, osA, isB, osB, isC, osC, innerN, alpha, flags);
}

static void launch_cvt(const float* in, __half* out, size_t n)
{
    int n4 = (int)(n / 4);
    int blocks = (n4 + 255) / 256;
    if (blocks > 8192) blocks = 8192;
    cvt_f2h_kernel<<<blocks, 256>>>(in, out, n4);
}

extern "C" void kernel_launch(void* const* d_in, const int* in_sizes, int n_in,
                              void* d_out, int out_size)
{
    const float* x     = (const float*)d_in[0];
    const float* freqs = (const float*)d_in[1];
    const float* Wqa   = (const float*)d_in[2];
    const float* qlnw  = (const float*)d_in[3];
    const float* Wqb   = (const float*)d_in[4];
    const float* Wkva  = (const float*)d_in[5];
    const float* kvlnw = (const float*)d_in[6];
    const float* Wkvb  = (const float*)d_in[7];
    const float* Wo    = (const float*)d_in[8];
    float* out = (float*)d_out;

    cudaFuncSetAttribute(gemm_h, cudaFuncAttributeMaxDynamicSharedMemorySize, SMEM_BYTES);

    float *qa, *kva, *scores;
    __half *xh, *wqah, *wqbh, *wkvah, *wkvbh, *woh;
    __half *qan, *kvc, *qfull, *kvb, *qh, *kh, *vhT, *probs, *attn;
    cudaGetSymbolAddress((void**)&qa,     g_qa);
    cudaGetSymbolAddress((void**)&kva,    g_kva);
    cudaGetSymbolAddress((void**)&scores, g_scores);
    cudaGetSymbolAddress((void**)&xh,     g_xh);
    cudaGetSymbolAddress((void**)&wqah,   g_wqah);
    cudaGetSymbolAddress((void**)&wqbh,   g_wqbh);
    cudaGetSymbolAddress((void**)&wkvah,  g_wkvah);
    cudaGetSymbolAddress((void**)&wkvbh,  g_wkvbh);
    cudaGetSymbolAddress((void**)&woh,    g_woh);
    cudaGetSymbolAddress((void**)&qan,    g_qan);
    cudaGetSymbolAddress((void**)&kvc,    g_kvc);
    cudaGetSymbolAddress((void**)&qfull,  g_qfull);
    cudaGetSymbolAddress((void**)&kvb,    g_kvb);
    cudaGetSymbolAddress((void**)&qh,     g_qh);
    cudaGetSymbolAddress((void**)&kh,     g_kh);
    cudaGetSymbolAddress((void**)&vhT,    g_vhT);
    cudaGetSymbolAddress((void**)&probs,  g_probs);
    cudaGetSymbolAddress((void**)&attn,   g_attn);

    const float SCALE = 1.0f / sqrtf((float)D_QK);
    const int CAUSAL = 1, KLIMIT = 2, HOUT = 4;

    // 0. convert inputs to fp16
    launch_cvt(x,    xh,    (size_t)BS * D_);
    launch_cvt(Wqa,  wqah,  (size_t)Q_LORA * D_);
    launch_cvt(Wqb,  wqbh,  (size_t)H_ * D_QK * Q_LORA);
    launch_cvt(Wkva, wkvah, (size_t)(KV_LORA + D_ROPE) * D_);
    launch_cvt(Wkvb, wkvbh, (size_t)H_ * (D_NOPE + D_V) * KV_LORA);
    launch_cvt(Wo,   woh,   (size_t)D_ * H_ * D_V);

    // 1. q_a = x @ Wqa^T                   [4096,1536] K=2048 -> fp32
    launch_gemm(xh, wqah, qa, BS, Q_LORA, D_, D_, D_, Q_LORA,
                0, 0, 0, 0, 0, 0, 1, 1, 1.0f, 0);
    // 2. RMSNorm q_a -> half
    rmsnorm_kernel<<<BS, 256>>>(qa, qlnw, qan, Q_LORA, Q_LORA, Q_LORA);
    // 3. q_full = q_a_n @ Wqb^T            [4096,3072] K=1536 -> half
    launch_gemm(qan, wqbh, qfull, BS, H_ * D_QK, Q_LORA, Q_LORA, Q_LORA, H_ * D_QK,
                0, 0, 0, 0, 0, 0, 1, 1, 1.0f, HOUT);
    // 4. kv_a = x @ Wkva^T                 [4096,576] K=2048 -> fp32 (ragged N)
    launch_gemm(xh, wkvah, kva, BS, KV_LORA + D_ROPE, D_, D_, D_, KV_LORA + D_ROPE,
                0, 0, 0, 0, 0, 0, 1, 1, 1.0f, 0);
    // 5. RMSNorm kv_c -> half
    rmsnorm_kernel<<<BS, 256>>>(kva, kvlnw, kvc, KV_LORA, KV_LORA + D_ROPE, KV_LORA);
    // 6. kv_b = kv_c @ Wkvb^T              [4096,4096] K=512 -> half
    launch_gemm(kvc, wkvbh, kvb, BS, H_ * (D_NOPE + D_V), KV_LORA, KV_LORA, KV_LORA,
                H_ * (D_NOPE + D_V),
                0, 0, 0, 0, 0, 0, 1, 1, 1.0f, HOUT);
    // 7. RoPE + assemble (half; V transposed to [b,h,d,s])
    assemble_kernel<<<dim3(BS, H_), 128>>>(qfull, kva, kvb, freqs, qh, kh, vhT);
    // 8. scores = SCALE * Q @ K^T -> fp32, causal-skipped, batched over (b,h)
    {
        long long isQ = (long long)S_ * D_QK;
        long long isS = (long long)S_ * S_;
        launch_gemm(qh, kh, scores, S_, S_, D_QK, D_QK, D_QK, S_,
                    isQ, isQ * H_, isQ, isQ * H_, isS, isS * H_, H_, BH,
                    SCALE, CAUSAL);
    }
    // 9. causal softmax -> half probs (zeroed tail)
    softmax_kernel<<<dim3(S_, BH), 256>>>(scores, probs);
    // 10. attn = P @ V^T (NT via transposed V), K bounded per M-tile -> half
    {
        long long isS = (long long)S_ * S_;
        long long isV = (long long)D_V * S_;
        launch_gemm(probs, vhT, attn, S_, D_V, S_, S_, S_, H_ * D_V,
                    isS, isS * H_, isV, isV * H_,
                    (long long)D_V, (long long)S_ * (H_ * D_V), H_, BH,
                    1.0f, KLIMIT | HOUT);
    }
    // 11. out = attn @ Wo^T                [4096,2048] K=2048 -> fp32
    launch_gemm(attn, woh, out, BS, D_, H_ * D_V, H_ * D_V, H_ * D_V, D_,
                0, 0, 0, 0, 0, 0, 1, 1, 1.0f, 0);
}

// round 10
// speedup vs baseline: 7.6904x; 1.3419x over previous
#include <cuda_runtime.h>
#include <cuda.h>
#include <cuda_fp16.h>
#include <math.h>
#include <cstdint>

// ---------------- problem constants ----------------
constexpr int B_ = 2;
constexpr int S_ = 2048;
constexpr int D_ = 2048;
constexpr int H_ = 16;
constexpr int Q_LORA = 1536;
constexpr int KV_LORA = 512;
constexpr int D_NOPE = 128;
constexpr int D_ROPE = 64;
constexpr int D_QK = D_NOPE + D_ROPE;   // 192
constexpr int D_V = 128;
constexpr int BS = B_ * S_;             // 4096
constexpr int BH = B_ * H_;             // 32
constexpr int NPROJ1 = Q_LORA + KV_LORA + D_ROPE;   // 2112

// ---------------- scratch (device globals) ----------------
__device__ float  g_proj1[(size_t)BS * NPROJ1];            // [q_a | kv_c_raw | k_pe_raw]
__device__ __half g_xh   [(size_t)BS * D_];
__device__ __half g_wcomb[(size_t)NPROJ1 * D_];            // [Wqa ; Wkva]
__device__ __half g_wqbh [(size_t)H_ * D_QK * Q_LORA];
__device__ __half g_wkvbh[(size_t)H_ * (D_NOPE + D_V) * KV_LORA];
__device__ __half g_woh  [(size_t)D_ * H_ * D_V];
__device__ __half g_qan  [(size_t)BS * Q_LORA];
__device__ __half g_kvc  [(size_t)BS * KV_LORA];
__device__ __half g_qfull[(size_t)BS * (H_ * D_QK)];
__device__ __half g_kvb  [(size_t)BS * (H_ * (D_NOPE + D_V))];
__device__ __half g_qh   [(size_t)BH * S_ * D_QK];
__device__ __half g_kh   [(size_t)BH * S_ * D_QK];
__device__ __half g_vhT  [(size_t)BH * D_V * S_];          // [b,h,d,s]
__device__ __half g_attn [(size_t)BS * (H_ * D_V)];

// ---------------- PTX helpers ----------------
__device__ __forceinline__ void mma_f16(float* c, const uint32_t* a, uint32_t b0, uint32_t b1) {
    asm volatile(
        "mma.sync.aligned.m16n8k16.row.col.f32.f16.f16.f32 "
        "{%0,%1,%2,%3}, {%4,%5,%6,%7}, {%8,%9}, {%0,%1,%2,%3};"
        : "+f"(c[0]), "+f"(c[1]), "+f"(c[2]), "+f"(c[3])
        : "r"(a[0]), "r"(a[1]), "r"(a[2]), "r"(a[3]), "r"(b0), "r"(b1));
}
__device__ __forceinline__ void ldsm4(uint32_t* r, uint32_t addr) {
    asm volatile("ldmatrix.sync.aligned.m8n8.x4.shared.b16 {%0,%1,%2,%3}, [%4];"
                 : "=r"(r[0]), "=r"(r[1]), "=r"(r[2]), "=r"(r[3]) : "r"(addr));
}
__device__ __forceinline__ void cp16(uint32_t dst, const void* src, int bytes) {
    asm volatile("cp.async.cg.shared.global [%0], [%1], 16, %2;"
                 :: "r"(dst), "l"(src), "r"(bytes));
}
#define CP_COMMIT() asm volatile("cp.async.commit_group;" ::: "memory")
#define CP_WAIT(n)  asm volatile("cp.async.wait_group %0;" :: "n"(n) : "memory")

__device__ __forceinline__ uint32_t h2u(float a, float b) {
    __half2 h = __floats2half2_rn(a, b);
    return *(uint32_t*)&h;
}

// ---------------- fp16 mma.sync GEMM, cp.async 3-stage (unchanged, validated) ----------------
// C[M,N] = alpha * A[M,K] * B[N,K]^T  flags bit2: C is __half.
#define STAGES   3
#define TILE_B   16384
#define STAGE_B  (2 * TILE_B)
#define SMEM_BYTES (STAGES * STAGE_B)     // 98304

__global__ void __launch_bounds__(256, 2) gemm_h(
    const __half* __restrict__ A, const __half* __restrict__ Bm, void* __restrict__ Cv,
    int M, int N, int K, int lda, int ldb, int ldc,
    float alpha, int flags)
{
    extern __shared__ __align__(16) char smc[];
    int t = threadIdx.x;
    int wid = t >> 5, lane = t & 31;
    int wm = wid & 3;
    int wn = wid >> 2;
    int lr = lane >> 2, lc = lane & 3;

    int m0 = blockIdx.y * 128;
    int n0 = blockIdx.x * 128;
    int NK = K >> 6;

    const __half* Abase = A + (long long)m0 * lda;
    const __half* Bbase = Bm + (long long)n0 * ldb;
    int nvB = N - n0; if (nvB > 128) nvB = 128;

    uint32_t sb = (uint32_t)__cvta_generic_to_shared(smc);

    int crow[4], ckc[4];
    uint32_t cdst[4];
#pragma unroll
    for (int i = 0; i < 4; i++) {
        int idx = t + i * 256;
        crow[i] = idx >> 3;
        ckc[i]  = idx & 7;
        cdst[i] = (uint32_t)(crow[i] * 128 + ((ckc[i] ^ (crow[i] & 7)) << 4));
    }

    auto issue = [&](int stage, int k0) {
        uint32_t dA = sb + (uint32_t)(stage * STAGE_B);
        uint32_t dB = dA + TILE_B;
#pragma unroll
        for (int i = 0; i < 4; i++) {
            int row = crow[i];
            cp16(dA + cdst[i], Abase + (long long)row * lda + k0 + ckc[i] * 8, 16);
            int brow = (row < nvB) ? row : 0;
            cp16(dB + cdst[i], Bbase + (long long)brow * ldb + k0 + ckc[i] * 8,
                 (row < nvB) ? 16 : 0);
        }
    };

    int aRow0 = wm * 32 + (lane & 15);
    int aSel  = (lane >> 4) & 1;
    int bRow0 = wn * 64 + (lane & 7) + (((lane >> 4) & 1) << 3);
    int bSel  = (lane >> 3) & 1;

    float acc[2][8][4];
#pragma unroll
    for (int i = 0; i < 2; i++)
#pragma unroll
        for (int j = 0; j < 8; j++)
#pragma unroll
            for (int k = 0; k < 4; k++) acc[i][j][k] = 0.f;

    issue(0, 0); CP_COMMIT();
    if (NK > 1) issue(1, 64);
    CP_COMMIT();
    int fetch = 2;

    for (int kt = 0; kt < NK; kt++) {
        CP_WAIT(1);
        __syncthreads();
        if (fetch < NK) issue(fetch % STAGES, fetch << 6);
        CP_COMMIT();
        fetch++;

        uint32_t sA = sb + (uint32_t)((kt % STAGES) * STAGE_B);
        uint32_t sB = sA + TILE_B;
#pragma unroll
        for (int ks = 0; ks < 4; ks++) {
            uint32_t a[2][4];
#pragma unroll
            for (int mf = 0; mf < 2; mf++) {
                int row = aRow0 + mf * 16;
                uint32_t addr = sA + row * 128 + ((((ks << 1) | aSel) ^ (row & 7)) << 4);
                ldsm4(a[mf], addr);
            }
#pragma unroll
            for (int nf2 = 0; nf2 < 4; nf2++) {
                int row = bRow0 + nf2 * 16;
                uint32_t addr = sB + row * 128 + ((((ks << 1) | bSel) ^ (row & 7)) << 4);
                uint32_t b[4];
                ldsm4(b, addr);
                mma_f16(acc[0][2 * nf2],     a[0], b[0], b[1]);
                mma_f16(acc[1][2 * nf2],     a[1], b[0], b[1]);
                mma_f16(acc[0][2 * nf2 + 1], a[0], b[2], b[3]);
                mma_f16(acc[1][2 * nf2 + 1], a[1], b[2], b[3]);
            }
        }
    }

    bool hout = (flags & 4) != 0;
#pragma unroll
    for (int mf = 0; mf < 2; mf++) {
        int r0 = m0 + wm * 32 + mf * 16 + lr;
#pragma unroll
        for (int nf = 0; nf < 8; nf++) {
            int gn = n0 + wn * 64 + nf * 8 + 2 * lc;
            if (gn < N) {
                float v0 = alpha * acc[mf][nf][0], v1 = alpha * acc[mf][nf][1];
                float v2 = alpha * acc[mf][nf][2], v3 = alpha * acc[mf][nf][3];
                if (hout) {
                    __half* C = (__half*)Cv;
                    *(__half2*)(C + (long long)r0 * ldc + gn) = __floats2half2_rn(v0, v1);
                    *(__half2*)(C + (long long)(r0 + 8) * ldc + gn) = __floats2half2_rn(v2, v3);
                } else {
                    float* C = (float*)Cv;
                    *(float2*)(C + (long long)r0 * ldc + gn) = make_float2(v0, v1);
                    *(float2*)(C + (long long)(r0 + 8) * ldc + gn) = make_float2(v2, v3);
                }
            }
        }
    }
}

// ---------------- fused flash attention (fp16 mma, online softmax) ----------------
// grid (16, BH); CTA 256 thr / 8 warps; warp owns 16 q-rows (full row -> warp-local softmax).
// smem: Q[128x192h] + 2x K[128x192h] + 2x V[128(d)x128(s)h]
#define FQ_B  49152
#define FK_B  49152
#define FV_B  32768
#define FSMEM (FQ_B + 2 * FK_B + 2 * FV_B)    // 212992

__global__ void __launch_bounds__(256, 1) flash_kernel(
    const __half* __restrict__ qh, const __half* __restrict__ kh,
    const __half* __restrict__ vhT, __half* __restrict__ attn, float scale)
{
    extern __shared__ __align__(16) char sm[];
    int t = threadIdx.x, wid = t >> 5, lane = t & 31;
    int qt = (int)gridDim.x - 1 - (int)blockIdx.x;     // longest tiles first
    int bh = blockIdx.y;
    int b = bh >> 4, h = bh & 15;
    int q0 = qt * 128;
    int wrow = wid * 16;
    int lr = lane >> 2, lc = lane & 3;

    const __half* Qg = qh + ((long long)bh * S_ + q0) * D_QK;
    const __half* Kg = kh + (long long)bh * S_ * D_QK;
    const __half* Vg = vhT + (long long)bh * D_V * S_;

    uint32_t sb = (uint32_t)__cvta_generic_to_shared(sm);
    uint32_t sQ  = sb;
    uint32_t sK0 = sb + FQ_B;
    uint32_t sV0 = sb + FQ_B + 2 * FK_B;

    // Q load (group 0): 128 rows x 24 chunks(16B), swizzled within 8-chunk groups
#pragma unroll
    for (int i = 0; i < 12; i++) {
        int c = i * 256 + t;
        int row = c / 24, ch = c % 24;
        uint32_t sw = (uint32_t)((ch & ~7) | ((ch & 7) ^ (row & 7)));
        cp16(sQ + row * 384 + sw * 16, Qg + row * D_QK + ch * 8, 16);
    }
    CP_COMMIT();

    auto issueKV = [&](int kt2, int buf2) {
        uint32_t dK = sK0 + (uint32_t)buf2 * FK_B;
        uint32_t dV = sV0 + (uint32_t)buf2 * FV_B;
        const __half* Ks = Kg + (long long)(kt2 * 128) * D_QK;
        const __half* Vs = Vg + kt2 * 128;
#pragma unroll
        for (int i = 0; i < 12; i++) {
            int c = i * 256 + t;
            int row = c / 24, ch = c % 24;
            uint32_t sw = (uint32_t)((ch & ~7) | ((ch & 7) ^ (row & 7)));
            cp16(dK + row * 384 + sw * 16, Ks + row * D_QK + ch * 8, 16);
        }
#pragma unroll
        for (int i = 0; i < 8; i++) {
            int c = i * 256 + t;
            int row = c >> 4, ch = c & 15;
            uint32_t sw = (uint32_t)((ch & ~7) | ((ch & 7) ^ (row & 7)));
            cp16(dV + row * 256 + sw * 16, Vs + (long long)row * S_ + ch * 8, 16);
        }
    };

    issueKV(0, 0); CP_COMMIT();

    float o[16][4];
#pragma unroll
    for (int i = 0; i < 16; i++)
#pragma unroll
        for (int j = 0; j < 4; j++) o[i][j] = 0.f;
    float m0 = -1e30f, m1 = -1e30f, l0 = 0.f, l1 = 0.f;

    int aSel = (lane >> 4) & 1;
    int bSub = (lane & 7) + (((lane >> 4) & 1) << 3);
    int bSel = (lane >> 3) & 1;

    for (int kt = 0; kt <= qt; kt++) {
        int buf = kt & 1;
        if (kt < qt) { issueKV(kt + 1, buf ^ 1); CP_COMMIT(); CP_WAIT(1); }
        else         { CP_WAIT(0); }
        __syncthreads();

        uint32_t sK = sK0 + (uint32_t)buf * FK_B;
        uint32_t sV = sV0 + (uint32_t)buf * FV_B;

        // ---- S = Q K^T (m16 x n128 per warp, K-dim 192) ----
        float s[16][4];
#pragma unroll
        for (int i = 0; i < 16; i++)
#pragma unroll
            for (int j = 0; j < 4; j++) s[i][j] = 0.f;
#pragma unroll
        for (int ks = 0; ks < 12; ks++) {
            uint32_t a[4];
            {
                int r = wrow + (lane & 15);
                int ch = 2 * ks + aSel;
                uint32_t sw = (uint32_t)((ch & ~7) | ((ch & 7) ^ (r & 7)));
                ldsm4(a, sQ + r * 384 + sw * 16);
            }
#pragma unroll
            for (int nf2 = 0; nf2 < 8; nf2++) {
                int r = nf2 * 16 + bSub;
                int ch = 2 * ks + bSel;
                uint32_t sw = (uint32_t)((ch & ~7) | ((ch & 7) ^ (r & 7)));
                uint32_t bf[4];
                ldsm4(bf, sK + r * 384 + sw * 16);
                mma_f16(s[2 * nf2],     a, bf[0], bf[1]);
                mma_f16(s[2 * nf2 + 1], a, bf[2], bf[3]);
            }
        }

        // ---- scale + causal mask (diag tile) ----
#pragma unroll
        for (int nf = 0; nf < 16; nf++)
#pragma unroll
            for (int j = 0; j < 4; j++) s[nf][j] *= scale;
        if (kt == qt) {
            int row0 = q0 + wrow + lr;
            int colb = q0 + 2 * lc;
#pragma unroll
            for (int nf = 0; nf < 16; nf++) {
                int c0 = colb + nf * 8;
                if (c0 > row0)         s[nf][0] = -1e30f;
                if (c0 + 1 > row0)     s[nf][1] = -1e30f;
                if (c0 > row0 + 8)     s[nf][2] = -1e30f;
                if (c0 + 1 > row0 + 8) s[nf][3] = -1e30f;
            }
        }

        // ---- online softmax (warp-local; 4 lanes share a row) ----
        float mx0 = -1e30f, mx1 = -1e30f;
#pragma unroll
        for (int nf = 0; nf < 16; nf++) {
            mx0 = fmaxf(mx0, fmaxf(s[nf][0], s[nf][1]));
            mx1 = fmaxf(mx1, fmaxf(s[nf][2], s[nf][3]));
        }
        mx0 = fmaxf(mx0, __shfl_xor_sync(0xffffffffu, mx0, 1));
        mx0 = fmaxf(mx0, __shfl_xor_sync(0xffffffffu, mx0, 2));
        mx1 = fmaxf(mx1, __shfl_xor_sync(0xffffffffu, mx1, 1));
        mx1 = fmaxf(mx1, __shfl_xor_sync(0xffffffffu, mx1, 2));
        float mn0 = fmaxf(m0, mx0), mn1 = fmaxf(m1, mx1);
        float al0 = __expf(m0 - mn0), al1 = __expf(m1 - mn1);
        m0 = mn0; m1 = mn1;
        float sum0 = 0.f, sum1 = 0.f;
#pragma unroll
        for (int nf = 0; nf < 16; nf++) {
            float p0 = __expf(s[nf][0] - mn0);
            float p1 = __expf(s[nf][1] - mn0);
            float p2 = __expf(s[nf][2] - mn1);
            float p3 = __expf(s[nf][3] - mn1);
            s[nf][0] = p0; s[nf][1] = p1; s[nf][2] = p2; s[nf][3] = p3;
            sum0 += p0 + p1; sum1 += p2 + p3;
        }
        sum0 += __shfl_xor_sync(0xffffffffu, sum0, 1);
        sum0 += __shfl_xor_sync(0xffffffffu, sum0, 2);
        sum1 += __shfl_xor_sync(0xffffffffu, sum1, 1);
        sum1 += __shfl_xor_sync(0xffffffffu, sum1, 2);
        l0 = l0 * al0 + sum0;
        l1 = l1 * al1 + sum1;
#pragma unroll
        for (int nf = 0; nf < 16; nf++) {
            o[nf][0] *= al0; o[nf][1] *= al0;
            o[nf][2] *= al1; o[nf][3] *= al1;
        }

        // ---- P (regs, exact A-fragment layout) @ V^T ----
#pragma unroll
        for (int j = 0; j < 8; j++) {
            uint32_t pa[4];
            pa[0] = h2u(s[2 * j][0],     s[2 * j][1]);
            pa[1] = h2u(s[2 * j][2],     s[2 * j][3]);
            pa[2] = h2u(s[2 * j + 1][0], s[2 * j + 1][1]);
            pa[3] = h2u(s[2 * j + 1][2], s[2 * j + 1][3]);
#pragma unroll
            for (int nd2 = 0; nd2 < 8; nd2++) {
                int r = nd2 * 16 + bSub;
                int ch = 2 * j + bSel;
                uint32_t sw = (uint32_t)((ch & ~7) | ((ch & 7) ^ (r & 7)));
                uint32_t bf[4];
                ldsm4(bf, sV + r * 256 + sw * 16);
                mma_f16(o[2 * nd2],     pa, bf[0], bf[1]);
                mma_f16(o[2 * nd2 + 1], pa, bf[2], bf[3]);
            }
        }
        __syncthreads();
    }

    // ---- normalize + store ----
    float il0 = 1.f / l0, il1 = 1.f / l1;
    int sg = q0 + wrow + lr;
    __half* a0 = attn + ((long long)(b * S_ + sg) * (H_ * D_V)) + h * D_V;
    __half* a1 = a0 + (long long)8 * (H_ * D_V);
#pragma unroll
    for (int nf = 0; nf < 16; nf++) {
        int d = nf * 8 + 2 * lc;
        *(__half2*)(a0 + d) = __floats2half2_rn(o[nf][0] * il0, o[nf][1] * il0);
        *(__half2*)(a1 + d) = __floats2half2_rn(o[nf][2] * il1, o[nf][3] * il1);
    }
}

// ---------------- fp32 -> fp16 convert ----------------
__global__ void cvt_f2h_kernel(const float* __restrict__ in, __half* __restrict__ out, int n4)
{
    int i = blockIdx.x * blockDim.x + threadIdx.x;
    int stride = gridDim.x * blockDim.x;
    for (; i < n4; i += stride) {
        float4 v = ((const float4*)in)[i];
        __half2 h0 = __floats2half2_rn(v.x, v.y);
        __half2 h1 = __floats2half2_rn(v.z, v.w);
        *(uint2*)(out + (size_t)i * 4) = make_uint2(*(uint32_t*)&h0, *(uint32_t*)&h1);
    }
}

// ---------------- RMSNorm (fp32 in strided, fp16 out) ----------------
__global__ void rmsnorm_kernel(const float* __restrict__ in, const float* __restrict__ w,
                               __half* __restrict__ out, int width, int in_stride, int out_stride)
{
    long long row = blockIdx.x;
    const float* x = in + row * in_stride;
    __half* o = out + row * out_stride;
    __shared__ float red[256];
    int t = threadIdx.x;
    float ss = 0.f;
    for (int i = t; i < width; i += 256) { float v = x[i]; ss += v * v; }
    red[t] = ss;
    __syncthreads();
    for (int s = 128; s > 0; s >>= 1) {
        if (t < s) red[t] += red[t + s];
        __syncthreads();
    }
    float scale = rsqrtf(red[0] / (float)width + 1e-6f);
    for (int i = t; i < width; i += 256) o[i] = __float2half_rn(x[i] * scale * w[i]);
}

// ---------------- RoPE + head assembly ----------------
__global__ void assemble_kernel(const __half* __restrict__ q_full, const float* __restrict__ proj1,
                                const __half* __restrict__ kv_b, const float* __restrict__ freqs,
                                __half* __restrict__ qh, __half* __restrict__ kh,
                                __half* __restrict__ vhT)
{
    int bs = blockIdx.x;
    int h  = blockIdx.y;
    int s  = bs & (S_ - 1);
    int b  = bs >> 11;
    const float* fr = freqs + (long long)s * D_ROPE;
    long long hd = ((long long)(b * H_ + h) * S_ + s);
    __half* qo = qh + hd * D_QK;
    __half* ko = kh + hd * D_QK;
    __half* vo = vhT + ((long long)(b * H_ + h) * D_V) * S_;
    const __half* qi  = q_full + (long long)bs * (H_ * D_QK) + h * D_QK;
    const __half* kvb = kv_b  + (long long)bs * (H_ * (D_NOPE + D_V)) + h * (D_NOPE + D_V);
    const float* kpe  = proj1 + (long long)bs * NPROJ1 + (Q_LORA + KV_LORA);

    int t = threadIdx.x;       // 128 threads
    qo[t] = qi[t];
    ko[t] = kvb[t];
    vo[(long long)t * S_ + s] = kvb[D_NOPE + t];
    if (t < 32) {
        float c  = fr[2 * t];
        float sn = fr[2 * t + 1];
        float x0 = __half2float(qi[D_NOPE + 2 * t]);
        float x1 = __half2float(qi[D_NOPE + 2 * t + 1]);
        qo[D_NOPE + 2 * t]     = __float2half_rn(x0 * c - x1 * sn);
        qo[D_NOPE + 2 * t + 1] = __float2half_rn(x0 * sn + x1 * c);
        float y0 = kpe[2 * t];
        float y1 = kpe[2 * t + 1];
        ko[D_NOPE + 2 * t]     = __float2half_rn(y0 * c - y1 * sn);
        ko[D_NOPE + 2 * t + 1] = __float2half_rn(y0 * sn + y1 * c);
    }
}

// ---------------- launch helpers ----------------
static void launch_gemm(const __half* A, const __half* Bm, void* C,
                        int M, int N, int K, int lda, int ldb, int ldc,
                        float alpha, int flags)
{
    dim3 grid((N + 127) / 128, (M + 127) / 128, 1);
    gemm_h<<<grid, 256, SMEM_BYTES>>>(A, Bm, C, M, N, K, lda, ldb, ldc, alpha, flags);
}

static void launch_cvt(const float* in, __half* out, size_t n)
{
    int n4 = (int)(n / 4);
    int blocks = (n4 + 255) / 256;
    if (blocks > 8192) blocks = 8192;
    cvt_f2h_kernel<<<blocks, 256>>>(in, out, n4);
}

extern "C" void kernel_launch(void* const* d_in, const int* in_sizes, int n_in,
                              void* d_out, int out_size)
{
    const float* x     = (const float*)d_in[0];
    const float* freqs = (const float*)d_in[1];
    const float* Wqa   = (const float*)d_in[2];
    const float* qlnw  = (const float*)d_in[3];
    const float* Wqb   = (const float*)d_in[4];
    const float* Wkva  = (const float*)d_in[5];
    const float* kvlnw = (const float*)d_in[6];
    const float* Wkvb  = (const float*)d_in[7];
    const float* Wo    = (const float*)d_in[8];
    float* out = (float*)d_out;

    cudaFuncSetAttribute(gemm_h, cudaFuncAttributeMaxDynamicSharedMemorySize, SMEM_BYTES);
    cudaFuncSetAttribute(flash_kernel, cudaFuncAttributeMaxDynamicSharedMemorySize, FSMEM);

    float *proj1;
    __half *xh, *wcomb, *wqbh, *wkvbh, *woh;
    __half *qan, *kvc, *qfull, *kvb, *qh, *kh, *vhT, *attn;
    cudaGetSymbolAddress((void**)&proj1,  g_proj1);
    cudaGetSymbolAddress((void**)&xh,     g_xh);
    cudaGetSymbolAddress((void**)&wcomb,  g_wcomb);
    cudaGetSymbolAddress((void**)&wqbh,   g_wqbh);
    cudaGetSymbolAddress((void**)&wkvbh,  g_wkvbh);
    cudaGetSymbolAddress((void**)&woh,    g_woh);
    cudaGetSymbolAddress((void**)&qan,    g_qan);
    cudaGetSymbolAddress((void**)&kvc,    g_kvc);
    cudaGetSymbolAddress((void**)&qfull,  g_qfull);
    cudaGetSymbolAddress((void**)&kvb,    g_kvb);
    cudaGetSymbolAddress((void**)&qh,     g_qh);
    cudaGetSymbolAddress((void**)&kh,     g_kh);
    cudaGetSymbolAddress((void**)&vhT,    g_vhT);
    cudaGetSymbolAddress((void**)&attn,   g_attn);

    const float SCALE = 1.0f / sqrtf((float)D_QK);
    const int HOUT = 4;

    // 0. fp16 conversions (Wqa and Wkva concatenated into one weight matrix)
    launch_cvt(x,    xh,    (size_t)BS * D_);
    launch_cvt(Wqa,  wcomb, (size_t)Q_LORA * D_);
    launch_cvt(Wkva, wcomb + (size_t)Q_LORA * D_, (size_t)(KV_LORA + D_ROPE) * D_);
    launch_cvt(Wqb,  wqbh,  (size_t)H_ * D_QK * Q_LORA);
    launch_cvt(Wkvb, wkvbh, (size_t)H_ * (D_NOPE + D_V) * KV_LORA);
    launch_cvt(Wo,   woh,   (size_t)D_ * H_ * D_V);

    // 1. proj1 = x @ [Wqa;Wkva]^T          [4096,2112] K=2048 -> fp32
    launch_gemm(xh, wcomb, proj1, BS, NPROJ1, D_, D_, D_, NPROJ1, 1.0f, 0);
    // 2. RMSNorms -> half
    rmsnorm_kernel<<<BS, 256>>>(proj1, qlnw, qan, Q_LORA, NPROJ1, Q_LORA);
    rmsnorm_kernel<<<BS, 256>>>(proj1 + Q_LORA, kvlnw, kvc, KV_LORA, NPROJ1, KV_LORA);
    // 3. q_full = q_a_n @ Wqb^T            [4096,3072] K=1536 -> half
    launch_gemm(qan, wqbh, qfull, BS, H_ * D_QK, Q_LORA, Q_LORA, Q_LORA, H_ * D_QK,
                1.0f, HOUT);
    // 4. kv_b = kv_c @ Wkvb^T              [4096,4096] K=512 -> half
    launch_gemm(kvc, wkvbh, kvb, BS, H_ * (D_NOPE + D_V), KV_LORA, KV_LORA, KV_LORA,
                H_ * (D_NOPE + D_V), 1.0f, HOUT);
    // 5. RoPE + assemble (half; V transposed to [b,h,d,s])
    assemble_kernel<<<dim3(BS, H_), 128>>>(qfull, proj1, kvb, freqs, qh, kh, vhT);
    // 6. fused flash attention -> attn (half)
    flash_kernel<<<dim3(S_ / 128, BH), 256, FSMEM>>>(qh, kh, vhT, attn, SCALE);
    // 7. out = attn @ Wo^T                 [4096,2048] K=2048 -> fp32
    launch_gemm(attn, woh, out, BS, D_, H_ * D_V, H_ * D_V, H_ * D_V, D_, 1.0f, 0);
}

// round 11
// speedup vs baseline: 8.5653x; 1.1138x over previous
#include <cuda_runtime.h>
#include <cuda.h>
#include <cuda_fp16.h>
#include <math.h>
#include <cstdint>

// ---------------- problem constants ----------------
constexpr int B_ = 2;
constexpr int S_ = 2048;
constexpr int D_ = 2048;
constexpr int H_ = 16;
constexpr int Q_LORA = 1536;
constexpr int KV_LORA = 512;
constexpr int D_NOPE = 128;
constexpr int D_ROPE = 64;
constexpr int D_QK = D_NOPE + D_ROPE;   // 192
constexpr int D_V = 128;
constexpr int BS = B_ * S_;             // 4096
constexpr int BH = B_ * H_;             // 32
constexpr int NPROJ1 = Q_LORA + KV_LORA + D_ROPE;   // 2112

// ---------------- scratch (device globals) ----------------
__device__ __half g_proj1[(size_t)BS * NPROJ1];            // [q_a | kv_c_raw | k_pe_raw] (half)
__device__ __half g_xh   [(size_t)BS * D_];
__device__ __half g_wcomb[(size_t)NPROJ1 * D_];            // [Wqa ; Wkva]
__device__ __half g_wqbh [(size_t)H_ * D_QK * Q_LORA];
__device__ __half g_wkvbh[(size_t)H_ * (D_NOPE + D_V) * KV_LORA];
__device__ __half g_woh  [(size_t)D_ * H_ * D_V];
__device__ __half g_qan  [(size_t)BS * Q_LORA];
__device__ __half g_kvc  [(size_t)BS * KV_LORA];
__device__ __half g_qfull[(size_t)BS * (H_ * D_QK)];       // RoPE applied in-place
__device__ __half g_kvb  [(size_t)BS * (H_ * (D_NOPE + D_V))];
__device__ __half g_kpe  [(size_t)BS * D_ROPE];            // roped k_pe (shared across heads)
__device__ __half g_attn [(size_t)BS * (H_ * D_V)];

// ---------------- PTX helpers ----------------
__device__ __forceinline__ void mma_f16(float* c, const uint32_t* a, uint32_t b0, uint32_t b1) {
    asm volatile(
        "mma.sync.aligned.m16n8k16.row.col.f32.f16.f16.f32 "
        "{%0,%1,%2,%3}, {%4,%5,%6,%7}, {%8,%9}, {%0,%1,%2,%3};"
        : "+f"(c[0]), "+f"(c[1]), "+f"(c[2]), "+f"(c[3])
        : "r"(a[0]), "r"(a[1]), "r"(a[2]), "r"(a[3]), "r"(b0), "r"(b1));
}
__device__ __forceinline__ void ldsm4(uint32_t* r, uint32_t addr) {
    asm volatile("ldmatrix.sync.aligned.m8n8.x4.shared.b16 {%0,%1,%2,%3}, [%4];"
                 : "=r"(r[0]), "=r"(r[1]), "=r"(r[2]), "=r"(r[3]) : "r"(addr));
}
__device__ __forceinline__ void ldsm4t(uint32_t* r, uint32_t addr) {
    asm volatile("ldmatrix.sync.aligned.m8n8.x4.trans.shared.b16 {%0,%1,%2,%3}, [%4];"
                 : "=r"(r[0]), "=r"(r[1]), "=r"(r[2]), "=r"(r[3]) : "r"(addr));
}
__device__ __forceinline__ void cp16(uint32_t dst, const void* src, int bytes) {
    asm volatile("cp.async.cg.shared.global [%0], [%1], 16, %2;"
                 :: "r"(dst), "l"(src), "r"(bytes));
}
#define CP_COMMIT() asm volatile("cp.async.commit_group;" ::: "memory")
#define CP_WAIT(n)  asm volatile("cp.async.wait_group %0;" :: "n"(n) : "memory")

__device__ __forceinline__ uint32_t h2u(float a, float b) {
    __half2 h = __floats2half2_rn(a, b);
    return *(uint32_t*)&h;
}

// ---------------- fp16 mma.sync GEMM, cp.async 3-stage (validated R9/R10) ----------------
// C[M,N] = alpha * A[M,K] * B[N,K]^T  flags bit2: C is __half.
#define STAGES   3
#define TILE_B   16384
#define STAGE_B  (2 * TILE_B)
#define SMEM_BYTES (STAGES * STAGE_B)     // 98304

__global__ void __launch_bounds__(256, 2) gemm_h(
    const __half* __restrict__ A, const __half* __restrict__ Bm, void* __restrict__ Cv,
    int M, int N, int K, int lda, int ldb, int ldc,
    float alpha, int flags)
{
    extern __shared__ __align__(16) char smc[];
    int t = threadIdx.x;
    int wid = t >> 5, lane = t & 31;
    int wm = wid & 3;
    int wn = wid >> 2;
    int lr = lane >> 2, lc = lane & 3;

    int m0 = blockIdx.y * 128;
    int n0 = blockIdx.x * 128;
    int NK = K >> 6;

    const __half* Abase = A + (long long)m0 * lda;
    const __half* Bbase = Bm + (long long)n0 * ldb;
    int nvB = N - n0; if (nvB > 128) nvB = 128;

    uint32_t sb = (uint32_t)__cvta_generic_to_shared(smc);

    int crow[4], ckc[4];
    uint32_t cdst[4];
#pragma unroll
    for (int i = 0; i < 4; i++) {
        int idx = t + i * 256;
        crow[i] = idx >> 3;
        ckc[i]  = idx & 7;
        cdst[i] = (uint32_t)(crow[i] * 128 + ((ckc[i] ^ (crow[i] & 7)) << 4));
    }

    auto issue = [&](int stage, int k0) {
        uint32_t dA = sb + (uint32_t)(stage * STAGE_B);
        uint32_t dB = dA + TILE_B;
#pragma unroll
        for (int i = 0; i < 4; i++) {
            int row = crow[i];
            cp16(dA + cdst[i], Abase + (long long)row * lda + k0 + ckc[i] * 8, 16);
            int brow = (row < nvB) ? row : 0;
            cp16(dB + cdst[i], Bbase + (long long)brow * ldb + k0 + ckc[i] * 8,
                 (row < nvB) ? 16 : 0);
        }
    };

    int aRow0 = wm * 32 + (lane & 15);
    int aSel  = (lane >> 4) & 1;
    int bRow0 = wn * 64 + (lane & 7) + (((lane >> 4) & 1) << 3);
    int bSel  = (lane >> 3) & 1;

    float acc[2][8][4];
#pragma unroll
    for (int i = 0; i < 2; i++)
#pragma unroll
        for (int j = 0; j < 8; j++)
#pragma unroll
            for (int k = 0; k < 4; k++) acc[i][j][k] = 0.f;

    issue(0, 0); CP_COMMIT();
    if (NK > 1) issue(1, 64);
    CP_COMMIT();
    int fetch = 2;

    for (int kt = 0; kt < NK; kt++) {
        CP_WAIT(1);
        __syncthreads();
        if (fetch < NK) issue(fetch % STAGES, fetch << 6);
        CP_COMMIT();
        fetch++;

        uint32_t sA = sb + (uint32_t)((kt % STAGES) * STAGE_B);
        uint32_t sB = sA + TILE_B;
#pragma unroll
        for (int ks = 0; ks < 4; ks++) {
            uint32_t a[2][4];
#pragma unroll
            for (int mf = 0; mf < 2; mf++) {
                int row = aRow0 + mf * 16;
                uint32_t addr = sA + row * 128 + ((((ks << 1) | aSel) ^ (row & 7)) << 4);
                ldsm4(a[mf], addr);
            }
#pragma unroll
            for (int nf2 = 0; nf2 < 4; nf2++) {
                int row = bRow0 + nf2 * 16;
                uint32_t addr = sB + row * 128 + ((((ks << 1) | bSel) ^ (row & 7)) << 4);
                uint32_t b[4];
                ldsm4(b, addr);
                mma_f16(acc[0][2 * nf2],     a[0], b[0], b[1]);
                mma_f16(acc[1][2 * nf2],     a[1], b[0], b[1]);
                mma_f16(acc[0][2 * nf2 + 1], a[0], b[2], b[3]);
                mma_f16(acc[1][2 * nf2 + 1], a[1], b[2], b[3]);
            }
        }
    }

    bool hout = (flags & 4) != 0;
#pragma unroll
    for (int mf = 0; mf < 2; mf++) {
        int r0 = m0 + wm * 32 + mf * 16 + lr;
#pragma unroll
        for (int nf = 0; nf < 8; nf++) {
            int gn = n0 + wn * 64 + nf * 8 + 2 * lc;
            if (gn < N) {
                float v0 = alpha * acc[mf][nf][0], v1 = alpha * acc[mf][nf][1];
                float v2 = alpha * acc[mf][nf][2], v3 = alpha * acc[mf][nf][3];
                if (hout) {
                    __half* C = (__half*)Cv;
                    *(__half2*)(C + (long long)r0 * ldc + gn) = __floats2half2_rn(v0, v1);
                    *(__half2*)(C + (long long)(r0 + 8) * ldc + gn) = __floats2half2_rn(v2, v3);
                } else {
                    float* C = (float*)Cv;
                    *(float2*)(C + (long long)r0 * ldc + gn) = make_float2(v0, v1);
                    *(float2*)(C + (long long)(r0 + 8) * ldc + gn) = make_float2(v2, v3);
                }
            }
        }
    }
}

// ---------------- fused flash attention: reads producer layouts directly ----------------
// Q from qfull [bs, h, 192] (RoPE pre-applied); K-nope from kvb [bs, h, 256] cols 0..127;
// K-pe from kpe [bs, 64]; V from kvb cols 128..255 in natural [s,d] via ldmatrix.trans.
#define FQ_B  49152
#define FK_B  49152
#define FV_B  32768
#define FSMEM (FQ_B + 2 * FK_B + 2 * FV_B)    // 212992

__global__ void __launch_bounds__(256, 1) flash_kernel(
    const __half* __restrict__ qfull, const __half* __restrict__ kvb,
    const __half* __restrict__ kpe, __half* __restrict__ attn, float scale)
{
    extern __shared__ __align__(16) char sm[];
    int t = threadIdx.x, wid = t >> 5, lane = t & 31;
    int qt = (int)gridDim.x - 1 - (int)blockIdx.x;     // longest tiles first
    int bh = blockIdx.y;
    int b = bh >> 4, h = bh & 15;
    int q0 = qt * 128;
    int wrow = wid * 16;
    int lr = lane >> 2, lc = lane & 3;

    // producer-layout base pointers
    const __half* Qg = qfull + ((long long)(b * S_ + q0) * H_ + h) * D_QK;   // row stride 3072
    const __half* Kn = kvb + ((long long)(b * S_) * H_ + h) * 256;           // row stride 4096
    const __half* Pe = kpe + (long long)b * S_ * D_ROPE;                     // row stride 64

    uint32_t sb = (uint32_t)__cvta_generic_to_shared(sm);
    uint32_t sQ  = sb;
    uint32_t sK0 = sb + FQ_B;
    uint32_t sV0 = sb + FQ_B + 2 * FK_B;

    // Q load: 128 rows x 24 chunks(16B), swizzled within 8-chunk groups
#pragma unroll
    for (int i = 0; i < 12; i++) {
        int c = i * 256 + t;
        int row = c / 24, ch = c % 24;
        uint32_t sw = (uint32_t)((ch & ~7) | ((ch & 7) ^ (row & 7)));
        cp16(sQ + row * 384 + sw * 16, Qg + (long long)row * (H_ * D_QK) + ch * 8, 16);
    }
    CP_COMMIT();

    auto issueKV = [&](int kt2, int buf2) {
        uint32_t dK = sK0 + (uint32_t)buf2 * FK_B;
        uint32_t dV = sV0 + (uint32_t)buf2 * FV_B;
        const __half* Ks = Kn + (long long)(kt2 * 128) * (H_ * 256);
        const __half* Ps = Pe + (long long)(kt2 * 128) * D_ROPE;
        // K rows: 24 chunks = 16 nope (kvb) + 8 pe (kpe, broadcast over h)
#pragma unroll
        for (int i = 0; i < 12; i++) {
            int c = i * 256 + t;
            int row = c / 24, ch = c % 24;
            uint32_t sw = (uint32_t)((ch & ~7) | ((ch & 7) ^ (row & 7)));
            const __half* src = (ch < 16)
                ? (Ks + (long long)row * (H_ * 256) + ch * 8)
                : (Ps + row * D_ROPE + (ch - 16) * 8);
            cp16(dK + row * 384 + sw * 16, src, 16);
        }
        // V rows (natural [s, d]): 16 chunks from kvb cols 128..255
#pragma unroll
        for (int i = 0; i < 8; i++) {
            int c = i * 256 + t;
            int row = c >> 4, ch = c & 15;
            uint32_t sw = (uint32_t)((ch & ~7) | ((ch & 7) ^ (row & 7)));
            cp16(dV + row * 256 + sw * 16,
                 Ks + (long long)row * (H_ * 256) + 128 + ch * 8, 16);
        }
    };

    issueKV(0, 0); CP_COMMIT();

    float o[16][4];
#pragma unroll
    for (int i = 0; i < 16; i++)
#pragma unroll
        for (int j = 0; j < 4; j++) o[i][j] = 0.f;
    float m0 = -1e30f, m1 = -1e30f, l0 = 0.f, l1 = 0.f;

    int aSel = (lane >> 4) & 1;
    int bSub = (lane & 7) + (((lane >> 4) & 1) << 3);
    int bSel = (lane >> 3) & 1;
    // V trans-ldmatrix lane mapping: m0..m3 = (d0-7,s0-7),(d0-7,s8-15),(d8-15,s0-7),(d8-15,s8-15)
    int vs_lane = lane & 15;           // s offset within 16-group
    int vd_half = (lane >> 4) & 1;     // +8 d chunk group

    for (int kt = 0; kt <= qt; kt++) {
        int buf = kt & 1;
        if (kt < qt) { issueKV(kt + 1, buf ^ 1); CP_COMMIT(); CP_WAIT(1); }
        else         { CP_WAIT(0); }
        __syncthreads();

        uint32_t sK = sK0 + (uint32_t)buf * FK_B;
        uint32_t sV = sV0 + (uint32_t)buf * FV_B;

        // ---- S = Q K^T (m16 x n128 per warp, K-dim 192) ----
        float s[16][4];
#pragma unroll
        for (int i = 0; i < 16; i++)
#pragma unroll
            for (int j = 0; j < 4; j++) s[i][j] = 0.f;
#pragma unroll
        for (int ks = 0; ks < 12; ks++) {
            uint32_t a[4];
            {
                int r = wrow + (lane & 15);
                int ch = 2 * ks + aSel;
                uint32_t sw = (uint32_t)((ch & ~7) | ((ch & 7) ^ (r & 7)));
                ldsm4(a, sQ + r * 384 + sw * 16);
            }
#pragma unroll
            for (int nf2 = 0; nf2 < 8; nf2++) {
                int r = nf2 * 16 + bSub;
                int ch = 2 * ks + bSel;
                uint32_t sw = (uint32_t)((ch & ~7) | ((ch & 7) ^ (r & 7)));
                uint32_t bf[4];
                ldsm4(bf, sK + r * 384 + sw * 16);
                mma_f16(s[2 * nf2],     a, bf[0], bf[1]);
                mma_f16(s[2 * nf2 + 1], a, bf[2], bf[3]);
            }
        }

        // ---- scale + causal mask (diag tile) ----
#pragma unroll
        for (int nf = 0; nf < 16; nf++)
#pragma unroll
            for (int j = 0; j < 4; j++) s[nf][j] *= scale;
        if (kt == qt) {
            int row0 = q0 + wrow + lr;
            int colb = q0 + 2 * lc;
#pragma unroll
            for (int nf = 0; nf < 16; nf++) {
                int c0 = colb + nf * 8;
                if (c0 > row0)         s[nf][0] = -1e30f;
                if (c0 + 1 > row0)     s[nf][1] = -1e30f;
                if (c0 > row0 + 8)     s[nf][2] = -1e30f;
                if (c0 + 1 > row0 + 8) s[nf][3] = -1e30f;
            }
        }

        // ---- online softmax (warp-local; 4 lanes share a row) ----
        float mx0 = -1e30f, mx1 = -1e30f;
#pragma unroll
        for (int nf = 0; nf < 16; nf++) {
            mx0 = fmaxf(mx0, fmaxf(s[nf][0], s[nf][1]));
            mx1 = fmaxf(mx1, fmaxf(s[nf][2], s[nf][3]));
        }
        mx0 = fmaxf(mx0, __shfl_xor_sync(0xffffffffu, mx0, 1));
        mx0 = fmaxf(mx0, __shfl_xor_sync(0xffffffffu, mx0, 2));
        mx1 = fmaxf(mx1, __shfl_xor_sync(0xffffffffu, mx1, 1));
        mx1 = fmaxf(mx1, __shfl_xor_sync(0xffffffffu, mx1, 2));
        float mn0 = fmaxf(m0, mx0), mn1 = fmaxf(m1, mx1);
        float al0 = __expf(m0 - mn0), al1 = __expf(m1 - mn1);
        m0 = mn0; m1 = mn1;
        float sum0 = 0.f, sum1 = 0.f;
#pragma unroll
        for (int nf = 0; nf < 16; nf++) {
            float p0 = __expf(s[nf][0] - mn0);
            float p1 = __expf(s[nf][1] - mn0);
            float p2 = __expf(s[nf][2] - mn1);
            float p3 = __expf(s[nf][3] - mn1);
            s[nf][0] = p0; s[nf][1] = p1; s[nf][2] = p2; s[nf][3] = p3;
            sum0 += p0 + p1; sum1 += p2 + p3;
        }
        sum0 += __shfl_xor_sync(0xffffffffu, sum0, 1);
        sum0 += __shfl_xor_sync(0xffffffffu, sum0, 2);
        sum1 += __shfl_xor_sync(0xffffffffu, sum1, 1);
        sum1 += __shfl_xor_sync(0xffffffffu, sum1, 2);
        l0 = l0 * al0 + sum0;
        l1 = l1 * al1 + sum1;
#pragma unroll
        for (int nf = 0; nf < 16; nf++) {
            o[nf][0] *= al0; o[nf][1] *= al0;
            o[nf][2] *= al1; o[nf][3] *= al1;
        }

        // ---- P (regs) @ V, with V fragments via trans-ldmatrix from [s,d] tiles ----
#pragma unroll
        for (int j = 0; j < 8; j++) {
            uint32_t pa[4];
            pa[0] = h2u(s[2 * j][0],     s[2 * j][1]);
            pa[1] = h2u(s[2 * j][2],     s[2 * j][3]);
            pa[2] = h2u(s[2 * j + 1][0], s[2 * j + 1][1]);
            pa[3] = h2u(s[2 * j + 1][2], s[2 * j + 1][3]);
            int s_off = 16 * j + vs_lane;
#pragma unroll
            for (int nd2 = 0; nd2 < 8; nd2++) {
                int d_chunk = nd2 * 2 + vd_half;
                uint32_t sw = (uint32_t)((d_chunk & ~7) | ((d_chunk & 7) ^ (s_off & 7)));
                uint32_t bf[4];
                ldsm4t(bf, sV + s_off * 256 + sw * 16);
                mma_f16(o[2 * nd2],     pa, bf[0], bf[1]);
                mma_f16(o[2 * nd2 + 1], pa, bf[2], bf[3]);
            }
        }
        __syncthreads();
    }

    // ---- normalize + store ----
    float il0 = 1.f / l0, il1 = 1.f / l1;
    int sg = q0 + wrow + lr;
    __half* a0 = attn + ((long long)(b * S_ + sg) * (H_ * D_V)) + h * D_V;
    __half* a1 = a0 + (long long)8 * (H_ * D_V);
#pragma unroll
    for (int nf = 0; nf < 16; nf++) {
        int d = nf * 8 + 2 * lc;
        *(__half2*)(a0 + d) = __floats2half2_rn(o[nf][0] * il0, o[nf][1] * il0);
        *(__half2*)(a1 + d) = __floats2half2_rn(o[nf][2] * il1, o[nf][3] * il1);
    }
}

// ---------------- fp32 -> fp16 convert ----------------
__global__ void cvt_f2h_kernel(const float* __restrict__ in, __half* __restrict__ out, int n4)
{
    int i = blockIdx.x * blockDim.x + threadIdx.x;
    int stride = gridDim.x * blockDim.x;
    for (; i < n4; i += stride) {
        float4 v = ((const float4*)in)[i];
        __half2 h0 = __floats2half2_rn(v.x, v.y);
        __half2 h1 = __floats2half2_rn(v.z, v.w);
        *(uint2*)(out + (size_t)i * 4) = make_uint2(*(uint32_t*)&h0, *(uint32_t*)&h1);
    }
}

// ---------------- fused dual RMSNorm (half in strided, half out) ----------------
__global__ void rmsnorm2_kernel(const __half* __restrict__ proj1,
                                const float* __restrict__ qw, const float* __restrict__ kw,
                                __half* __restrict__ qan, __half* __restrict__ kvc)
{
    long long row = blockIdx.x;
    int which = blockIdx.y;
    int width = which ? KV_LORA : Q_LORA;
    const __half* x = proj1 + row * NPROJ1 + (which ? Q_LORA : 0);
    const float* w = which ? kw : qw;
    __half* o = which ? (kvc + row * KV_LORA) : (qan + row * Q_LORA);
    __shared__ float red[256];
    int t = threadIdx.x;
    float ss = 0.f;
    for (int i = t; i < width; i += 256) { float v = __half2float(x[i]); ss += v * v; }
    red[t] = ss;
    __syncthreads();
    for (int s = 128; s > 0; s >>= 1) {
        if (t < s) red[t] += red[t + s];
        __syncthreads();
    }
    float scale = rsqrtf(red[0] / (float)width + 1e-6f);
    for (int i = t; i < width; i += 256)
        o[i] = __float2half_rn(__half2float(x[i]) * scale * w[i]);
}

// ---------------- RoPE: in-place on qfull pe slices + kpe extraction ----------------
__global__ void rope_kernel(__half* __restrict__ qfull, const __half* __restrict__ proj1,
                            const float* __restrict__ freqs, __half* __restrict__ kpe)
{
    int bs = blockIdx.x;
    int s  = bs & (S_ - 1);
    const float* fr = freqs + (long long)s * D_ROPE;
    int t = threadIdx.x;       // 128 threads; 544 work items (16 heads x 32 pairs + 32 kpe pairs)
    for (int i = t; i < 544; i += 128) {
        if (i < 512) {
            int h = i >> 5, p = i & 31;
            __half* q = qfull + ((long long)bs * H_ + h) * D_QK + D_NOPE + 2 * p;
            float c  = fr[2 * p], sn = fr[2 * p + 1];
            float x0 = __half2float(q[0]);
            float x1 = __half2float(q[1]);
            q[0] = __float2half_rn(x0 * c - x1 * sn);
            q[1] = __float2half_rn(x0 * sn + x1 * c);
        } else {
            int p = i - 512;
            const __half* kp = proj1 + (long long)bs * NPROJ1 + (Q_LORA + KV_LORA) + 2 * p;
            float c  = fr[2 * p], sn = fr[2 * p + 1];
            float y0 = __half2float(kp[0]);
            float y1 = __half2float(kp[1]);
            __half* ko = kpe + (long long)bs * D_ROPE + 2 * p;
            ko[0] = __float2half_rn(y0 * c - y1 * sn);
            ko[1] = __float2half_rn(y0 * sn + y1 * c);
        }
    }
}

// ---------------- launch helpers ----------------
static void launch_gemm(const __half* A, const __half* Bm, void* C,
                        int M, int N, int K, int lda, int ldb, int ldc,
                        float alpha, int flags)
{
    dim3 grid((N + 127) / 128, (M + 127) / 128, 1);
    gemm_h<<<grid, 256, SMEM_BYTES>>>(A, Bm, C, M, N, K, lda, ldb, ldc, alpha, flags);
}

static void launch_cvt(const float* in, __half* out, size_t n)
{
    int n4 = (int)(n / 4);
    int blocks = (n4 + 255) / 256;
    if (blocks > 8192) blocks = 8192;
    cvt_f2h_kernel<<<blocks, 256>>>(in, out, n4);
}

extern "C" void kernel_launch(void* const* d_in, const int* in_sizes, int n_in,
                              void* d_out, int out_size)
{
    const float* x     = (const float*)d_in[0];
    const float* freqs = (const float*)d_in[1];
    const float* Wqa   = (const float*)d_in[2];
    const float* qlnw  = (const float*)d_in[3];
    const float* Wqb   = (const float*)d_in[4];
    const float* Wkva  = (const float*)d_in[5];
    const float* kvlnw = (const float*)d_in[6];
    const float* Wkvb  = (const float*)d_in[7];
    const float* Wo    = (const float*)d_in[8];
    float* out = (float*)d_out;

    cudaFuncSetAttribute(gemm_h, cudaFuncAttributeMaxDynamicSharedMemorySize, SMEM_BYTES);
    cudaFuncSetAttribute(flash_kernel, cudaFuncAttributeMaxDynamicSharedMemorySize, FSMEM);

    __half *proj1, *xh, *wcomb, *wqbh, *wkvbh, *woh;
    __half *qan, *kvc, *qfull, *kvb, *kpe, *attn;
    cudaGetSymbolAddress((void**)&proj1,  g_proj1);
    cudaGetSymbolAddress((void**)&xh,     g_xh);
    cudaGetSymbolAddress((void**)&wcomb,  g_wcomb);
    cudaGetSymbolAddress((void**)&wqbh,   g_wqbh);
    cudaGetSymbolAddress((void**)&wkvbh,  g_wkvbh);
    cudaGetSymbolAddress((void**)&woh,    g_woh);
    cudaGetSymbolAddress((void**)&qan,    g_qan);
    cudaGetSymbolAddress((void**)&kvc,    g_kvc);
    cudaGetSymbolAddress((void**)&qfull,  g_qfull);
    cudaGetSymbolAddress((void**)&kvb,    g_kvb);
    cudaGetSymbolAddress((void**)&kpe,    g_kpe);
    cudaGetSymbolAddress((void**)&attn,   g_attn);

    const float SCALE = 1.0f / sqrtf((float)D_QK);
    const int HOUT = 4;

    // 0. fp16 conversions (Wqa and Wkva concatenated into one weight matrix)
    launch_cvt(x,    xh,    (size_t)BS * D_);
    launch_cvt(Wqa,  wcomb, (size_t)Q_LORA * D_);
    launch_cvt(Wkva, wcomb + (size_t)Q_LORA * D_, (size_t)(KV_LORA + D_ROPE) * D_);
    launch_cvt(Wqb,  wqbh,  (size_t)H_ * D_QK * Q_LORA);
    launch_cvt(Wkvb, wkvbh, (size_t)H_ * (D_NOPE + D_V) * KV_LORA);
    launch_cvt(Wo,   woh,   (size_t)D_ * H_ * D_V);

    // 1. proj1 = x @ [Wqa;Wkva]^T          [4096,2112] K=2048 -> half
    launch_gemm(xh, wcomb, proj1, BS, NPROJ1, D_, D_, D_, NPROJ1, 1.0f, HOUT);
    // 2. fused RMSNorms -> half
    rmsnorm2_kernel<<<dim3(BS, 2), 256>>>(proj1, qlnw, kvlnw, qan, kvc);
    // 3. q_full = q_a_n @ Wqb^T            [4096,3072] K=1536 -> half
    launch_gemm(qan, wqbh, qfull, BS, H_ * D_QK, Q_LORA, Q_LORA, Q_LORA, H_ * D_QK,
                1.0f, HOUT);
    // 4. kv_b = kv_c @ Wkvb^T              [4096,4096] K=512 -> half
    launch_gemm(kvc, wkvbh, kvb, BS, H_ * (D_NOPE + D_V), KV_LORA, KV_LORA, KV_LORA,
                H_ * (D_NOPE + D_V), 1.0f, HOUT);
    // 5. RoPE (in-place on qfull; kpe extracted from proj1)
    rope_kernel<<<BS, 128>>>(qfull, proj1, freqs, kpe);
    // 6. fused flash attention (producer layouts, no staging) -> attn (half)
    flash_kernel<<<dim3(S_ / 128, BH), 256, FSMEM>>>(qfull, kvb, kpe, attn, SCALE);
    // 7. out = attn @ Wo^T                 [4096,2048] K=2048 -> fp32
    launch_gemm(attn, woh, out, BS, D_, H_ * D_V, H_ * D_V, H_ * D_V, D_, 1.0f, 0);
}

// round 12
// speedup vs baseline: 9.0683x; 1.0587x over previous
#include <cuda_runtime.h>
#include <cuda.h>
#include <cuda_fp16.h>
#include <math.h>
#include <cstdint>

// ---------------- problem constants ----------------
constexpr int B_ = 2;
constexpr int S_ = 2048;
constexpr int D_ = 2048;
constexpr int H_ = 16;
constexpr int Q_LORA = 1536;
constexpr int KV_LORA = 512;
constexpr int D_NOPE = 128;
constexpr int D_ROPE = 64;
constexpr int D_QK = D_NOPE + D_ROPE;   // 192
constexpr int D_V = 128;
constexpr int BS = B_ * S_;             // 4096
constexpr int BH = B_ * H_;             // 32
constexpr int NPROJ1 = Q_LORA + KV_LORA + D_ROPE;   // 2112

// ---------------- scratch (device globals) ----------------
__device__ __half g_proj1[(size_t)BS * NPROJ1];            // [q_a | kv_c_raw | k_pe_raw] (half)
__device__ __half g_xh   [(size_t)BS * D_];
__device__ __half g_wcomb[(size_t)NPROJ1 * D_];            // [Wqa ; Wkva]
__device__ __half g_wqbh [(size_t)H_ * D_QK * Q_LORA];
__device__ __half g_wkvbh[(size_t)H_ * (D_NOPE + D_V) * KV_LORA];
__device__ __half g_woh  [(size_t)D_ * H_ * D_V];
__device__ __half g_qan  [(size_t)BS * Q_LORA];
__device__ __half g_kvc  [(size_t)BS * KV_LORA];
__device__ __half g_qfull[(size_t)BS * (H_ * D_QK)];       // RoPE applied in-place
__device__ __half g_kvb  [(size_t)BS * (H_ * (D_NOPE + D_V))];
__device__ __half g_kpe  [(size_t)BS * D_ROPE];            // roped k_pe (shared across heads)
__device__ __half g_attn [(size_t)BS * (H_ * D_V)];

// ---------------- PTX helpers ----------------
__device__ __forceinline__ void mma_f16(float* c, const uint32_t* a, uint32_t b0, uint32_t b1) {
    asm volatile(
        "mma.sync.aligned.m16n8k16.row.col.f32.f16.f16.f32 "
        "{%0,%1,%2,%3}, {%4,%5,%6,%7}, {%8,%9}, {%0,%1,%2,%3};"
        : "+f"(c[0]), "+f"(c[1]), "+f"(c[2]), "+f"(c[3])
        : "r"(a[0]), "r"(a[1]), "r"(a[2]), "r"(a[3]), "r"(b0), "r"(b1));
}
__device__ __forceinline__ void ldsm4(uint32_t* r, uint32_t addr) {
    asm volatile("ldmatrix.sync.aligned.m8n8.x4.shared.b16 {%0,%1,%2,%3}, [%4];"
                 : "=r"(r[0]), "=r"(r[1]), "=r"(r[2]), "=r"(r[3]) : "r"(addr));
}
__device__ __forceinline__ void ldsm4t(uint32_t* r, uint32_t addr) {
    asm volatile("ldmatrix.sync.aligned.m8n8.x4.trans.shared.b16 {%0,%1,%2,%3}, [%4];"
                 : "=r"(r[0]), "=r"(r[1]), "=r"(r[2]), "=r"(r[3]) : "r"(addr));
}
__device__ __forceinline__ void cp16(uint32_t dst, const void* src, int bytes) {
    asm volatile("cp.async.cg.shared.global [%0], [%1], 16, %2;"
                 :: "r"(dst), "l"(src), "r"(bytes));
}
#define CP_COMMIT() asm volatile("cp.async.commit_group;" ::: "memory")
#define CP_WAIT(n)  asm volatile("cp.async.wait_group %0;" :: "n"(n) : "memory")

__device__ __forceinline__ uint32_t h2u(float a, float b) {
    __half2 h = __floats2half2_rn(a, b);
    return *(uint32_t*)&h;
}

// ---------------- fp16 mma.sync GEMM, cp.async 3-stage (validated R9-R11) ----------------
// C[M,N] = alpha * A[M,K] * B[N,K]^T  flags bit2: C is __half.
#define STAGES   3
#define TILE_B   16384
#define STAGE_B  (2 * TILE_B)
#define SMEM_BYTES (STAGES * STAGE_B)     // 98304

__global__ void __launch_bounds__(256, 2) gemm_h(
    const __half* __restrict__ A, const __half* __restrict__ Bm, void* __restrict__ Cv,
    int M, int N, int K, int lda, int ldb, int ldc,
    float alpha, int flags)
{
    extern __shared__ __align__(16) char smc[];
    int t = threadIdx.x;
    int wid = t >> 5, lane = t & 31;
    int wm = wid & 3;
    int wn = wid >> 2;
    int lr = lane >> 2, lc = lane & 3;

    int m0 = blockIdx.y * 128;
    int n0 = blockIdx.x * 128;
    int NK = K >> 6;

    const __half* Abase = A + (long long)m0 * lda;
    const __half* Bbase = Bm + (long long)n0 * ldb;
    int nvB = N - n0; if (nvB > 128) nvB = 128;

    uint32_t sb = (uint32_t)__cvta_generic_to_shared(smc);

    int crow[4], ckc[4];
    uint32_t cdst[4];
#pragma unroll
    for (int i = 0; i < 4; i++) {
        int idx = t + i * 256;
        crow[i] = idx >> 3;
        ckc[i]  = idx & 7;
        cdst[i] = (uint32_t)(crow[i] * 128 + ((ckc[i] ^ (crow[i] & 7)) << 4));
    }

    auto issue = [&](int stage, int k0) {
        uint32_t dA = sb + (uint32_t)(stage * STAGE_B);
        uint32_t dB = dA + TILE_B;
#pragma unroll
        for (int i = 0; i < 4; i++) {
            int row = crow[i];
            cp16(dA + cdst[i], Abase + (long long)row * lda + k0 + ckc[i] * 8, 16);
            int brow = (row < nvB) ? row : 0;
            cp16(dB + cdst[i], Bbase + (long long)brow * ldb + k0 + ckc[i] * 8,
                 (row < nvB) ? 16 : 0);
        }
    };

    int aRow0 = wm * 32 + (lane & 15);
    int aSel  = (lane >> 4) & 1;
    int bRow0 = wn * 64 + (lane & 7) + (((lane >> 4) & 1) << 3);
    int bSel  = (lane >> 3) & 1;

    float acc[2][8][4];
#pragma unroll
    for (int i = 0; i < 2; i++)
#pragma unroll
        for (int j = 0; j < 8; j++)
#pragma unroll
            for (int k = 0; k < 4; k++) acc[i][j][k] = 0.f;

    issue(0, 0); CP_COMMIT();
    if (NK > 1) issue(1, 64);
    CP_COMMIT();
    int fetch = 2;

    for (int kt = 0; kt < NK; kt++) {
        CP_WAIT(1);
        __syncthreads();
        if (fetch < NK) issue(fetch % STAGES, fetch << 6);
        CP_COMMIT();
        fetch++;

        uint32_t sA = sb + (uint32_t)((kt % STAGES) * STAGE_B);
        uint32_t sB = sA + TILE_B;
#pragma unroll
        for (int ks = 0; ks < 4; ks++) {
            uint32_t a[2][4];
#pragma unroll
            for (int mf = 0; mf < 2; mf++) {
                int row = aRow0 + mf * 16;
                uint32_t addr = sA + row * 128 + ((((ks << 1) | aSel) ^ (row & 7)) << 4);
                ldsm4(a[mf], addr);
            }
#pragma unroll
            for (int nf2 = 0; nf2 < 4; nf2++) {
                int row = bRow0 + nf2 * 16;
                uint32_t addr = sB + row * 128 + ((((ks << 1) | bSel) ^ (row & 7)) << 4);
                uint32_t b[4];
                ldsm4(b, addr);
                mma_f16(acc[0][2 * nf2],     a[0], b[0], b[1]);
                mma_f16(acc[1][2 * nf2],     a[1], b[0], b[1]);
                mma_f16(acc[0][2 * nf2 + 1], a[0], b[2], b[3]);
                mma_f16(acc[1][2 * nf2 + 1], a[1], b[2], b[3]);
            }
        }
    }

    bool hout = (flags & 4) != 0;
#pragma unroll
    for (int mf = 0; mf < 2; mf++) {
        int r0 = m0 + wm * 32 + mf * 16 + lr;
#pragma unroll
        for (int nf = 0; nf < 8; nf++) {
            int gn = n0 + wn * 64 + nf * 8 + 2 * lc;
            if (gn < N) {
                float v0 = alpha * acc[mf][nf][0], v1 = alpha * acc[mf][nf][1];
                float v2 = alpha * acc[mf][nf][2], v3 = alpha * acc[mf][nf][3];
                if (hout) {
                    __half* C = (__half*)Cv;
                    *(__half2*)(C + (long long)r0 * ldc + gn) = __floats2half2_rn(v0, v1);
                    *(__half2*)(C + (long long)(r0 + 8) * ldc + gn) = __floats2half2_rn(v2, v3);
                } else {
                    float* C = (float*)Cv;
                    *(float2*)(C + (long long)r0 * ldc + gn) = make_float2(v0, v1);
                    *(float2*)(C + (long long)(r0 + 8) * ldc + gn) = make_float2(v2, v3);
                }
            }
        }
    }
}

// ---------------- fused flash attention (validated R11) ----------------
#define FQ_B  49152
#define FK_B  49152
#define FV_B  32768
#define FSMEM (FQ_B + 2 * FK_B + 2 * FV_B)    // 212992

__global__ void __launch_bounds__(256, 1) flash_kernel(
    const __half* __restrict__ qfull, const __half* __restrict__ kvb,
    const __half* __restrict__ kpe, __half* __restrict__ attn, float scale)
{
    extern __shared__ __align__(16) char sm[];
    int t = threadIdx.x, wid = t >> 5, lane = t & 31;
    int qt = (int)gridDim.x - 1 - (int)blockIdx.x;     // longest tiles first
    int bh = blockIdx.y;
    int b = bh >> 4, h = bh & 15;
    int q0 = qt * 128;
    int wrow = wid * 16;
    int lr = lane >> 2, lc = lane & 3;

    const __half* Qg = qfull + ((long long)(b * S_ + q0) * H_ + h) * D_QK;
    const __half* Kn = kvb + ((long long)(b * S_) * H_ + h) * 256;
    const __half* Pe = kpe + (long long)b * S_ * D_ROPE;

    uint32_t sb = (uint32_t)__cvta_generic_to_shared(sm);
    uint32_t sQ  = sb;
    uint32_t sK0 = sb + FQ_B;
    uint32_t sV0 = sb + FQ_B + 2 * FK_B;

#pragma unroll
    for (int i = 0; i < 12; i++) {
        int c = i * 256 + t;
        int row = c / 24, ch = c % 24;
        uint32_t sw = (uint32_t)((ch & ~7) | ((ch & 7) ^ (row & 7)));
        cp16(sQ + row * 384 + sw * 16, Qg + (long long)row * (H_ * D_QK) + ch * 8, 16);
    }
    CP_COMMIT();

    auto issueKV = [&](int kt2, int buf2) {
        uint32_t dK = sK0 + (uint32_t)buf2 * FK_B;
        uint32_t dV = sV0 + (uint32_t)buf2 * FV_B;
        const __half* Ks = Kn + (long long)(kt2 * 128) * (H_ * 256);
        const __half* Ps = Pe + (long long)(kt2 * 128) * D_ROPE;
#pragma unroll
        for (int i = 0; i < 12; i++) {
            int c = i * 256 + t;
            int row = c / 24, ch = c % 24;
            uint32_t sw = (uint32_t)((ch & ~7) | ((ch & 7) ^ (row & 7)));
            const __half* src = (ch < 16)
                ? (Ks + (long long)row * (H_ * 256) + ch * 8)
                : (Ps + row * D_ROPE + (ch - 16) * 8);
            cp16(dK + row * 384 + sw * 16, src, 16);
        }
#pragma unroll
        for (int i = 0; i < 8; i++) {
            int c = i * 256 + t;
            int row = c >> 4, ch = c & 15;
            uint32_t sw = (uint32_t)((ch & ~7) | ((ch & 7) ^ (row & 7)));
            cp16(dV + row * 256 + sw * 16,
                 Ks + (long long)row * (H_ * 256) + 128 + ch * 8, 16);
        }
    };

    issueKV(0, 0); CP_COMMIT();

    float o[16][4];
#pragma unroll
    for (int i = 0; i < 16; i++)
#pragma unroll
        for (int j = 0; j < 4; j++) o[i][j] = 0.f;
    float m0 = -1e30f, m1 = -1e30f, l0 = 0.f, l1 = 0.f;

    int aSel = (lane >> 4) & 1;
    int bSub = (lane & 7) + (((lane >> 4) & 1) << 3);
    int bSel = (lane >> 3) & 1;
    int vs_lane = lane & 15;
    int vd_half = (lane >> 4) & 1;

    for (int kt = 0; kt <= qt; kt++) {
        int buf = kt & 1;
        if (kt < qt) { issueKV(kt + 1, buf ^ 1); CP_COMMIT(); CP_WAIT(1); }
        else         { CP_WAIT(0); }
        __syncthreads();

        uint32_t sK = sK0 + (uint32_t)buf * FK_B;
        uint32_t sV = sV0 + (uint32_t)buf * FV_B;

        float s[16][4];
#pragma unroll
        for (int i = 0; i < 16; i++)
#pragma unroll
            for (int j = 0; j < 4; j++) s[i][j] = 0.f;
#pragma unroll
        for (int ks = 0; ks < 12; ks++) {
            uint32_t a[4];
            {
                int r = wrow + (lane & 15);
                int ch = 2 * ks + aSel;
                uint32_t sw = (uint32_t)((ch & ~7) | ((ch & 7) ^ (r & 7)));
                ldsm4(a, sQ + r * 384 + sw * 16);
            }
#pragma unroll
            for (int nf2 = 0; nf2 < 8; nf2++) {
                int r = nf2 * 16 + bSub;
                int ch = 2 * ks + bSel;
                uint32_t sw = (uint32_t)((ch & ~7) | ((ch & 7) ^ (r & 7)));
                uint32_t bf[4];
                ldsm4(bf, sK + r * 384 + sw * 16);
                mma_f16(s[2 * nf2],     a, bf[0], bf[1]);
                mma_f16(s[2 * nf2 + 1], a, bf[2], bf[3]);
            }
        }

#pragma unroll
        for (int nf = 0; nf < 16; nf++)
#pragma unroll
            for (int j = 0; j < 4; j++) s[nf][j] *= scale;
        if (kt == qt) {
            int row0 = q0 + wrow + lr;
            int colb = q0 + 2 * lc;
#pragma unroll
            for (int nf = 0; nf < 16; nf++) {
                int c0 = colb + nf * 8;
                if (c0 > row0)         s[nf][0] = -1e30f;
                if (c0 + 1 > row0)     s[nf][1] = -1e30f;
                if (c0 > row0 + 8)     s[nf][2] = -1e30f;
                if (c0 + 1 > row0 + 8) s[nf][3] = -1e30f;
            }
        }

        float mx0 = -1e30f, mx1 = -1e30f;
#pragma unroll
        for (int nf = 0; nf < 16; nf++) {
            mx0 = fmaxf(mx0, fmaxf(s[nf][0], s[nf][1]));
            mx1 = fmaxf(mx1, fmaxf(s[nf][2], s[nf][3]));
        }
        mx0 = fmaxf(mx0, __shfl_xor_sync(0xffffffffu, mx0, 1));
        mx0 = fmaxf(mx0, __shfl_xor_sync(0xffffffffu, mx0, 2));
        mx1 = fmaxf(mx1, __shfl_xor_sync(0xffffffffu, mx1, 1));
        mx1 = fmaxf(mx1, __shfl_xor_sync(0xffffffffu, mx1, 2));
        float mn0 = fmaxf(m0, mx0), mn1 = fmaxf(m1, mx1);
        float al0 = __expf(m0 - mn0), al1 = __expf(m1 - mn1);
        m0 = mn0; m1 = mn1;
        float sum0 = 0.f, sum1 = 0.f;
#pragma unroll
        for (int nf = 0; nf < 16; nf++) {
            float p0 = __expf(s[nf][0] - mn0);
            float p1 = __expf(s[nf][1] - mn0);
            float p2 = __expf(s[nf][2] - mn1);
            float p3 = __expf(s[nf][3] - mn1);
            s[nf][0] = p0; s[nf][1] = p1; s[nf][2] = p2; s[nf][3] = p3;
            sum0 += p0 + p1; sum1 += p2 + p3;
        }
        sum0 += __shfl_xor_sync(0xffffffffu, sum0, 1);
        sum0 += __shfl_xor_sync(0xffffffffu, sum0, 2);
        sum1 += __shfl_xor_sync(0xffffffffu, sum1, 1);
        sum1 += __shfl_xor_sync(0xffffffffu, sum1, 2);
        l0 = l0 * al0 + sum0;
        l1 = l1 * al1 + sum1;
#pragma unroll
        for (int nf = 0; nf < 16; nf++) {
            o[nf][0] *= al0; o[nf][1] *= al0;
            o[nf][2] *= al1; o[nf][3] *= al1;
        }

#pragma unroll
        for (int j = 0; j < 8; j++) {
            uint32_t pa[4];
            pa[0] = h2u(s[2 * j][0],     s[2 * j][1]);
            pa[1] = h2u(s[2 * j][2],     s[2 * j][3]);
            pa[2] = h2u(s[2 * j + 1][0], s[2 * j + 1][1]);
            pa[3] = h2u(s[2 * j + 1][2], s[2 * j + 1][3]);
            int s_off = 16 * j + vs_lane;
#pragma unroll
            for (int nd2 = 0; nd2 < 8; nd2++) {
                int d_chunk = nd2 * 2 + vd_half;
                uint32_t sw = (uint32_t)((d_chunk & ~7) | ((d_chunk & 7) ^ (s_off & 7)));
                uint32_t bf[4];
                ldsm4t(bf, sV + s_off * 256 + sw * 16);
                mma_f16(o[2 * nd2],     pa, bf[0], bf[1]);
                mma_f16(o[2 * nd2 + 1], pa, bf[2], bf[3]);
            }
        }
        __syncthreads();
    }

    float il0 = 1.f / l0, il1 = 1.f / l1;
    int sg = q0 + wrow + lr;
    __half* a0 = attn + ((long long)(b * S_ + sg) * (H_ * D_V)) + h * D_V;
    __half* a1 = a0 + (long long)8 * (H_ * D_V);
#pragma unroll
    for (int nf = 0; nf < 16; nf++) {
        int d = nf * 8 + 2 * lc;
        *(__half2*)(a0 + d) = __floats2half2_rn(o[nf][0] * il0, o[nf][1] * il0);
        *(__half2*)(a1 + d) = __floats2half2_rn(o[nf][2] * il1, o[nf][3] * il1);
    }
}

// ---------------- fp32 -> fp16 convert ----------------
__global__ void cvt_f2h_kernel(const float* __restrict__ in, __half* __restrict__ out, int n4)
{
    int i = blockIdx.x * blockDim.x + threadIdx.x;
    int stride = gridDim.x * blockDim.x;
    for (; i < n4; i += stride) {
        float4 v = ((const float4*)in)[i];
        __half2 h0 = __floats2half2_rn(v.x, v.y);
        __half2 h1 = __floats2half2_rn(v.z, v.w);
        *(uint2*)(out + (size_t)i * 4) = make_uint2(*(uint32_t*)&h0, *(uint32_t*)&h1);
    }
}

// ---------------- fused dual RMSNorm ----------------
__global__ void rmsnorm2_kernel(const __half* __restrict__ proj1,
                                const float* __restrict__ qw, const float* __restrict__ kw,
                                __half* __restrict__ qan, __half* __restrict__ kvc)
{
    long long row = blockIdx.x;
    int which = blockIdx.y;
    int width = which ? KV_LORA : Q_LORA;
    const __half* x = proj1 + row * NPROJ1 + (which ? Q_LORA : 0);
    const float* w = which ? kw : qw;
    __half* o = which ? (kvc + row * KV_LORA) : (qan + row * Q_LORA);
    __shared__ float red[256];
    int t = threadIdx.x;
    float ss = 0.f;
    for (int i = t; i < width; i += 256) { float v = __half2float(x[i]); ss += v * v; }
    red[t] = ss;
    __syncthreads();
    for (int s = 128; s > 0; s >>= 1) {
        if (t < s) red[t] += red[t + s];
        __syncthreads();
    }
    float scale = rsqrtf(red[0] / (float)width + 1e-6f);
    for (int i = t; i < width; i += 256)
        o[i] = __float2half_rn(__half2float(x[i]) * scale * w[i]);
}

// ---------------- RoPE: in-place on qfull pe slices + kpe extraction ----------------
__global__ void rope_kernel(__half* __restrict__ qfull, const __half* __restrict__ proj1,
                            const float* __restrict__ freqs, __half* __restrict__ kpe)
{
    int bs = blockIdx.x;
    int s  = bs & (S_ - 1);
    const float* fr = freqs + (long long)s * D_ROPE;
    int t = threadIdx.x;
    for (int i = t; i < 544; i += 128) {
        if (i < 512) {
            int h = i >> 5, p = i & 31;
            __half* q = qfull + ((long long)bs * H_ + h) * D_QK + D_NOPE + 2 * p;
            float c  = fr[2 * p], sn = fr[2 * p + 1];
            float x0 = __half2float(q[0]);
            float x1 = __half2float(q[1]);
            q[0] = __float2half_rn(x0 * c - x1 * sn);
            q[1] = __float2half_rn(x0 * sn + x1 * c);
        } else {
            int p = i - 512;
            const __half* kp = proj1 + (long long)bs * NPROJ1 + (Q_LORA + KV_LORA) + 2 * p;
            float c  = fr[2 * p], sn = fr[2 * p + 1];
            float y0 = __half2float(kp[0]);
            float y1 = __half2float(kp[1]);
            __half* ko = kpe + (long long)bs * D_ROPE + 2 * p;
            ko[0] = __float2half_rn(y0 * c - y1 * sn);
            ko[1] = __float2half_rn(y0 * sn + y1 * c);
        }
    }
}

// ---------------- launch helpers ----------------
static void launch_gemm_s(cudaStream_t st, const __half* A, const __half* Bm, void* C,
                          int M, int N, int K, int lda, int ldb, int ldc,
                          float alpha, int flags)
{
    dim3 grid((N + 127) / 128, (M + 127) / 128, 1);
    gemm_h<<<grid, 256, SMEM_BYTES, st>>>(A, Bm, C, M, N, K, lda, ldb, ldc, alpha, flags);
}

static void launch_cvt_s(cudaStream_t st, const float* in, __half* out, size_t n)
{
    int n4 = (int)(n / 4);
    int blocks = (n4 + 255) / 256;
    if (blocks > 8192) blocks = 8192;
    cvt_f2h_kernel<<<blocks, 256, 0, st>>>(in, out, n4);
}

extern "C" void kernel_launch(void* const* d_in, const int* in_sizes, int n_in,
                              void* d_out, int out_size)
{
    const float* x     = (const float*)d_in[0];
    const float* freqs = (const float*)d_in[1];
    const float* Wqa   = (const float*)d_in[2];
    const float* qlnw  = (const float*)d_in[3];
    const float* Wqb   = (const float*)d_in[4];
    const float* Wkva  = (const float*)d_in[5];
    const float* kvlnw = (const float*)d_in[6];
    const float* Wkvb  = (const float*)d_in[7];
    const float* Wo    = (const float*)d_in[8];
    float* out = (float*)d_out;

    cudaFuncSetAttribute(gemm_h, cudaFuncAttributeMaxDynamicSharedMemorySize, SMEM_BYTES);
    cudaFuncSetAttribute(flash_kernel, cudaFuncAttributeMaxDynamicSharedMemorySize, FSMEM);

    __half *proj1, *xh, *wcomb, *wqbh, *wkvbh, *woh;
    __half *qan, *kvc, *qfull, *kvb, *kpe, *attn;
    cudaGetSymbolAddress((void**)&proj1,  g_proj1);
    cudaGetSymbolAddress((void**)&xh,     g_xh);
    cudaGetSymbolAddress((void**)&wcomb,  g_wcomb);
    cudaGetSymbolAddress((void**)&wqbh,   g_wqbh);
    cudaGetSymbolAddress((void**)&wkvbh,  g_wkvbh);
    cudaGetSymbolAddress((void**)&woh,    g_woh);
    cudaGetSymbolAddress((void**)&qan,    g_qan);
    cudaGetSymbolAddress((void**)&kvc,    g_kvc);
    cudaGetSymbolAddress((void**)&qfull,  g_qfull);
    cudaGetSymbolAddress((void**)&kvb,    g_kvb);
    cudaGetSymbolAddress((void**)&kpe,    g_kpe);
    cudaGetSymbolAddress((void**)&attn,   g_attn);

    const float SCALE = 1.0f / sqrtf((float)D_QK);
    const int HOUT = 4;
    cudaStream_t s0 = 0;

    // second stream + fork/join events (created per call; capturable pattern)
    cudaStream_t s2;
    cudaStreamCreateWithFlags(&s2, cudaStreamNonBlocking);
    cudaEvent_t eFork, eW, eN, e4;
    cudaEventCreateWithFlags(&eFork, cudaEventDisableTiming);
    cudaEventCreateWithFlags(&eW,    cudaEventDisableTiming);
    cudaEventCreateWithFlags(&eN,    cudaEventDisableTiming);
    cudaEventCreateWithFlags(&e4,    cudaEventDisableTiming);

    // fork s2 off the capture (NULL) stream
    cudaEventRecord(eFork, s0);
    cudaStreamWaitEvent(s2, eFork, 0);

    // s2: convert Wqb / Wkvb / Wo (needed by GEMM3 / GEMM4 / GEMM7)
    launch_cvt_s(s2, Wqb,  wqbh,  (size_t)H_ * D_QK * Q_LORA);
    launch_cvt_s(s2, Wkvb, wkvbh, (size_t)H_ * (D_NOPE + D_V) * KV_LORA);
    launch_cvt_s(s2, Wo,   woh,   (size_t)D_ * H_ * D_V);
    cudaEventRecord(eW, s2);

    // s0: convert x + [Wqa;Wkva], then GEMM1 + RMSNorms
    launch_cvt_s(s0, x,    xh,    (size_t)BS * D_);
    launch_cvt_s(s0, Wqa,  wcomb, (size_t)Q_LORA * D_);
    launch_cvt_s(s0, Wkva, wcomb + (size_t)Q_LORA * D_, (size_t)(KV_LORA + D_ROPE) * D_);
    // 1. proj1 = x @ [Wqa;Wkva]^T          [4096,2112] K=2048 -> half
    launch_gemm_s(s0, xh, wcomb, proj1, BS, NPROJ1, D_, D_, D_, NPROJ1, 1.0f, HOUT);
    // 2. fused RMSNorms -> half
    rmsnorm2_kernel<<<dim3(BS, 2), 256, 0, s0>>>(proj1, qlnw, kvlnw, qan, kvc);
    cudaEventRecord(eN, s0);

    // s2: GEMM4 (needs kvc from eN + wkvbh already on s2)
    cudaStreamWaitEvent(s2, eN, 0);
    // 4. kv_b = kv_c @ Wkvb^T              [4096,4096] K=512 -> half
    launch_gemm_s(s2, kvc, wkvbh, kvb, BS, H_ * (D_NOPE + D_V), KV_LORA, KV_LORA, KV_LORA,
                  H_ * (D_NOPE + D_V), 1.0f, HOUT);
    cudaEventRecord(e4, s2);

    // s0: GEMM3 (needs wqbh from eW), concurrent with GEMM4 on s2
    cudaStreamWaitEvent(s0, eW, 0);
    // 3. q_full = q_a_n @ Wqb^T            [4096,3072] K=1536 -> half
    launch_gemm_s(s0, qan, wqbh, qfull, BS, H_ * D_QK, Q_LORA, Q_LORA, Q_LORA, H_ * D_QK,
                  1.0f, HOUT);
    // 5. RoPE (needs GEMM3 + proj1; overlaps GEMM4 tail)
    rope_kernel<<<BS, 128, 0, s0>>>(qfull, proj1, freqs, kpe);

    // join: flash needs GEMM4 output
    cudaStreamWaitEvent(s0, e4, 0);
    // 6. fused flash attention -> attn (half)
    flash_kernel<<<dim3(S_ / 128, BH), 256, FSMEM, s0>>>(qfull, kvb, kpe, attn, SCALE);
    // 7. out = attn @ Wo^T                 [4096,2048] K=2048 -> fp32
    launch_gemm_s(s0, attn, woh, out, BS, D_, H_ * D_V, H_ * D_V, H_ * D_V, D_, 1.0f, 0);
}